// round 1
// baseline (speedup 1.0000x reference)
#include <cuda_runtime.h>

// ---------------------------------------------------------------------------
// TriangularAttention: B=2, S=48 -> N=2304, D=256, H=8, DH=32
// Round 0: fp32 baseline, flash-style fused attention, f32x2-packed FMA.
// ---------------------------------------------------------------------------

constexpr int B_  = 2;
constexpr int S_  = 48;
constexpr int D_  = 256;
constexpr int H_  = 8;
constexpr int DH_ = 32;
constexpr int N_  = S_ * S_;     // 2304
constexpr int M_  = B_ * N_;     // 4608 rows
constexpr int BH_ = B_ * H_;     // 16

// Scratch (device globals: no allocation allowed in kernel_launch)
__device__ float g_q[BH_ * N_ * DH_];    // [b*H+h][n][dh]
__device__ float g_k[BH_ * N_ * DH_];
__device__ float g_v[BH_ * N_ * DH_];
__device__ float g_ctx[M_ * D_];         // [b*N+n][d]

using u64 = unsigned long long;

__device__ __forceinline__ u64 pack2(float lo, float hi) {
    u64 r;
    asm("mov.b64 %0, {%1, %2};" : "=l"(r) : "f"(lo), "f"(hi));
    return r;
}
__device__ __forceinline__ void unpack2(u64 v, float& lo, float& hi) {
    unsigned a, b;
    asm("mov.b64 {%0, %1}, %2;" : "=r"(a), "=r"(b) : "l"(v));
    lo = __uint_as_float(a);
    hi = __uint_as_float(b);
}
// Packed 2-wide fp32 FMA (sm_103a): 2x FFMA throughput, ptxas won't emit this itself.
__device__ __forceinline__ u64 ffma2(u64 a, u64 b, u64 c) {
    u64 d;
    asm("fma.rn.f32x2 %0, %1, %2, %3;" : "=l"(d) : "l"(a), "l"(b), "l"(c));
    return d;
}
__device__ __forceinline__ u64 fmul2(u64 a, u64 b) {
    u64 d;
    asm("mul.rn.f32x2 %0, %1, %2;" : "=l"(d) : "l"(a), "l"(b));
    return d;
}

// ---------------------------------------------------------------------------
// GEMM: out[M,256] = A[M,256] @ W[256,256] + bias
// MODE 0: plain row-major out[m*256 + c]
// MODE 1: head-major out[((b*H+h)*N + n)*DH + dh] with c = h*32+dh, m = b*N+n
// Tiles: 64x64x16, 256 threads, 4x4 per thread via f32x2 pairs.
// ---------------------------------------------------------------------------
template <int HEADMAJOR>
__global__ __launch_bounds__(256) void gemm256_kernel(
    const float* __restrict__ A, const float* __restrict__ W,
    const float* __restrict__ bias, float* __restrict__ out)
{
    __shared__ float As[16][68];            // [k][m], padded (272B row, 16B aligned)
    __shared__ __align__(16) u64 Bs[16][32]; // [k][c/2] packed pairs

    const int t  = threadIdx.x;
    const int tx = t & 15;
    const int ty = t >> 4;
    const int c0 = blockIdx.x * 64;
    const int m0 = blockIdx.y * 64;

    u64 acc[4][2];
#pragma unroll
    for (int i = 0; i < 4; i++)
#pragma unroll
        for (int j = 0; j < 2; j++) acc[i][j] = pack2(0.f, 0.f);

    const int a_m  = t >> 2;          // 0..63
    const int a_k4 = (t & 3) * 4;     // 0,4,8,12
    const int b_k  = t >> 4;          // 0..15
    const int b_c4 = (t & 15) * 4;    // 0..60

    for (int k0 = 0; k0 < 256; k0 += 16) {
        float4 av = *(const float4*)&A[(size_t)(m0 + a_m) * 256 + k0 + a_k4];
        float4 wv = *(const float4*)&W[(size_t)(k0 + b_k) * 256 + c0 + b_c4];
        As[a_k4 + 0][a_m] = av.x;
        As[a_k4 + 1][a_m] = av.y;
        As[a_k4 + 2][a_m] = av.z;
        As[a_k4 + 3][a_m] = av.w;
        Bs[b_k][b_c4 / 2]     = pack2(wv.x, wv.y);
        Bs[b_k][b_c4 / 2 + 1] = pack2(wv.z, wv.w);
        __syncthreads();

#pragma unroll
        for (int k = 0; k < 16; k++) {
            float4 a = *(const float4*)&As[k][ty * 4];
            const ulonglong2 bb = *(const ulonglong2*)&Bs[k][tx * 2];
            u64 b0 = bb.x, b1 = bb.y;
            u64 a0 = pack2(a.x, a.x), a1 = pack2(a.y, a.y);
            u64 a2 = pack2(a.z, a.z), a3 = pack2(a.w, a.w);
            acc[0][0] = ffma2(a0, b0, acc[0][0]); acc[0][1] = ffma2(a0, b1, acc[0][1]);
            acc[1][0] = ffma2(a1, b0, acc[1][0]); acc[1][1] = ffma2(a1, b1, acc[1][1]);
            acc[2][0] = ffma2(a2, b0, acc[2][0]); acc[2][1] = ffma2(a2, b1, acc[2][1]);
            acc[3][0] = ffma2(a3, b0, acc[3][0]); acc[3][1] = ffma2(a3, b1, acc[3][1]);
        }
        __syncthreads();
    }

    const int c = c0 + tx * 4;
    float bv0 = bias[c], bv1 = bias[c + 1], bv2 = bias[c + 2], bv3 = bias[c + 3];

#pragma unroll
    for (int i = 0; i < 4; i++) {
        int m = m0 + ty * 4 + i;
        float l0, h0, l1, h1;
        unpack2(acc[i][0], l0, h0);
        unpack2(acc[i][1], l1, h1);
        float4 r = make_float4(l0 + bv0, h0 + bv1, l1 + bv2, h1 + bv3);
        if (HEADMAJOR) {
            int hh = c >> 5;          // head
            int dh = c & 31;          // within-head dim (4-aligned)
            int b  = m / N_;
            int n  = m - b * N_;
            *(float4*)&out[(((size_t)(b * H_ + hh)) * N_ + n) * DH_ + dh] = r;
        } else {
            *(float4*)&out[(size_t)m * 256 + c] = r;
        }
    }
}

// ---------------------------------------------------------------------------
// Flash attention: one thread owns one query row (q, o, m, l in registers).
// Grid (N/128, B*H), 128 threads. K/V streamed in 32-key SMEM tiles.
// ---------------------------------------------------------------------------
__global__ __launch_bounds__(128) void attn_kernel()
{
    constexpr int TK = 32;
    __shared__ __align__(16) u64 Ks[TK * 16];
    __shared__ __align__(16) u64 Vs[TK * 16];

    const int bh   = blockIdx.y;
    const int qrow = blockIdx.x * 128 + threadIdx.x;
    const int t    = threadIdx.x;

    const float* Qp    = g_q + ((size_t)bh * N_ + qrow) * DH_;
    const float* Kbase = g_k + (size_t)bh * N_ * DH_;
    const float* Vbase = g_v + (size_t)bh * N_ * DH_;
    const float scale  = 0.17677669529663687f;  // 1/sqrt(32)

    u64 q2[16];
#pragma unroll
    for (int i = 0; i < 8; i++) {
        float4 v = *(const float4*)&Qp[i * 4];
        q2[i * 2]     = pack2(v.x * scale, v.y * scale);
        q2[i * 2 + 1] = pack2(v.z * scale, v.w * scale);
    }

    float mrun = -1e30f, lrun = 0.f;
    u64 o2[16];
#pragma unroll
    for (int i = 0; i < 16; i++) o2[i] = pack2(0.f, 0.f);

    for (int k0 = 0; k0 < N_; k0 += TK) {
        // Tile (32 keys x 32 dims) is contiguous: 256 float4. 128 threads x 2.
        const float4* Ksrc = (const float4*)(Kbase + (size_t)k0 * DH_);
        const float4* Vsrc = (const float4*)(Vbase + (size_t)k0 * DH_);
        float4* Kd = (float4*)Ks;
        float4* Vd = (float4*)Vs;
        Kd[t]       = Ksrc[t];
        Kd[t + 128] = Ksrc[t + 128];
        Vd[t]       = Vsrc[t];
        Vd[t + 128] = Vsrc[t + 128];
        __syncthreads();

        float s[TK];
#pragma unroll 4
        for (int j = 0; j < TK; j++) {
            const ulonglong2* kr = (const ulonglong2*)(Ks + j * 16);
            u64 a0 = pack2(0.f, 0.f), a1 = pack2(0.f, 0.f);
#pragma unroll
            for (int i = 0; i < 8; i++) {
                ulonglong2 kk = kr[i];
                a0 = ffma2(q2[2 * i],     kk.x, a0);
                a1 = ffma2(q2[2 * i + 1], kk.y, a1);
            }
            float x0, x1, y0, y1;
            unpack2(a0, x0, x1);
            unpack2(a1, y0, y1);
            s[j] = (x0 + x1) + (y0 + y1);
        }

        float tmax = s[0];
#pragma unroll
        for (int j = 1; j < TK; j++) tmax = fmaxf(tmax, s[j]);
        float mnew = fmaxf(mrun, tmax);
        float corr = __expf(mrun - mnew);
        lrun *= corr;
        u64 corr2 = pack2(corr, corr);
#pragma unroll
        for (int i = 0; i < 16; i++) o2[i] = fmul2(o2[i], corr2);

#pragma unroll 4
        for (int j = 0; j < TK; j++) {
            float p = __expf(s[j] - mnew);
            lrun += p;
            u64 p2 = pack2(p, p);
            const ulonglong2* vr = (const ulonglong2*)(Vs + j * 16);
#pragma unroll
            for (int i = 0; i < 8; i++) {
                ulonglong2 vv = vr[i];
                o2[2 * i]     = ffma2(p2, vv.x, o2[2 * i]);
                o2[2 * i + 1] = ffma2(p2, vv.y, o2[2 * i + 1]);
            }
        }
        mrun = mnew;
        __syncthreads();
    }

    float inv = 1.0f / lrun;
    int b = bh / H_, h = bh % H_;
    float* outp = g_ctx + ((size_t)(b * N_) + qrow) * D_ + h * DH_;
#pragma unroll
    for (int i = 0; i < 8; i++) {
        float l0, h0, l1, h1;
        unpack2(o2[2 * i], l0, h0);
        unpack2(o2[2 * i + 1], l1, h1);
        *(float4*)&outp[i * 4] = make_float4(l0 * inv, h0 * inv, l1 * inv, h1 * inv);
    }
}

// ---------------------------------------------------------------------------
extern "C" void kernel_launch(void* const* d_in, const int* in_sizes, int n_in,
                              void* d_out, int out_size)
{
    const float* x  = (const float*)d_in[0];
    const float* Wq = (const float*)d_in[1];
    const float* bq = (const float*)d_in[2];
    const float* Wk = (const float*)d_in[3];
    const float* bk = (const float*)d_in[4];
    const float* Wv = (const float*)d_in[5];
    const float* bv = (const float*)d_in[6];
    const float* Wo = (const float*)d_in[7];
    const float* bo = (const float*)d_in[8];
    float* out = (float*)d_out;

    float *qp, *kp, *vp, *ctxp;
    cudaGetSymbolAddress((void**)&qp,   g_q);
    cudaGetSymbolAddress((void**)&kp,   g_k);
    cudaGetSymbolAddress((void**)&vp,   g_v);
    cudaGetSymbolAddress((void**)&ctxp, g_ctx);

    dim3 ggrid(256 / 64, M_ / 64);   // (4, 72)
    dim3 gblk(256);

    gemm256_kernel<1><<<ggrid, gblk>>>(x, Wq, bq, qp);
    gemm256_kernel<1><<<ggrid, gblk>>>(x, Wk, bk, kp);
    gemm256_kernel<1><<<ggrid, gblk>>>(x, Wv, bv, vp);

    dim3 agrid(N_ / 128, BH_);       // (18, 16)
    attn_kernel<<<agrid, 128>>>();

    gemm256_kernel<0><<<ggrid, gblk>>>(ctxp, Wo, bo, out);
}

// round 4
// speedup vs baseline: 2.9746x; 2.9746x over previous
#include <cuda_runtime.h>
#include <cstdint>

// ---------------------------------------------------------------------------
// TriangularAttention: B=2, S=48 -> N=2304, D=256, H=8, DH=32
// Round 3: mma.sync tf32 flash attention (sm_103-safe, no 'a' features);
//          fp32 f32x2 GEMMs unchanged from round 1.
// ---------------------------------------------------------------------------

constexpr int B_  = 2;
constexpr int S_  = 48;
constexpr int D_  = 256;
constexpr int H_  = 8;
constexpr int DH_ = 32;
constexpr int N_  = S_ * S_;     // 2304
constexpr int M_  = B_ * N_;     // 4608
constexpr int BH_ = B_ * H_;     // 16

__device__ float g_q[BH_ * N_ * DH_];    // [b*H+h][n][dh]
__device__ float g_k[BH_ * N_ * DH_];
__device__ float g_v[BH_ * N_ * DH_];
__device__ float g_ctx[M_ * D_];         // [b*N+n][d]

using u64 = unsigned long long;

// ---------------- f32x2 helpers (GEMM path) --------------------------------
__device__ __forceinline__ u64 pack2(float lo, float hi) {
    u64 r;
    asm("mov.b64 %0, {%1, %2};" : "=l"(r) : "f"(lo), "f"(hi));
    return r;
}
__device__ __forceinline__ void unpack2(u64 v, float& lo, float& hi) {
    unsigned a, b;
    asm("mov.b64 {%0, %1}, %2;" : "=r"(a), "=r"(b) : "l"(v));
    lo = __uint_as_float(a);
    hi = __uint_as_float(b);
}
__device__ __forceinline__ u64 ffma2(u64 a, u64 b, u64 c) {
    u64 d;
    asm("fma.rn.f32x2 %0, %1, %2, %3;" : "=l"(d) : "l"(a), "l"(b), "l"(c));
    return d;
}

// ---------------- mma.sync helpers -----------------------------------------
__device__ __forceinline__ uint32_t tf32r(float x) {   // round-to-nearest tf32
    uint32_t r;
    asm("cvt.rna.tf32.f32 %0, %1;" : "=r"(r) : "f"(x));
    return r;
}
__device__ __forceinline__ float ex2f(float x) {
    float y;
    asm("ex2.approx.ftz.f32 %0, %1;" : "=f"(y) : "f"(x));
    return y;
}
__device__ __forceinline__ void mma_tf32(float* d, const uint32_t* a,
                                         uint32_t b0, uint32_t b1) {
    asm volatile(
        "mma.sync.aligned.m16n8k8.row.col.f32.tf32.tf32.f32 "
        "{%0,%1,%2,%3}, {%4,%5,%6,%7}, {%8,%9}, {%0,%1,%2,%3};"
        : "+f"(d[0]), "+f"(d[1]), "+f"(d[2]), "+f"(d[3])
        : "r"(a[0]), "r"(a[1]), "r"(a[2]), "r"(a[3]), "r"(b0), "r"(b1));
}
__device__ __forceinline__ uint32_t fasu(float x) { return __float_as_uint(x); }

// ---------------------------------------------------------------------------
// GEMM (proven in round 1): out[M,256] = A[M,256] @ W[256,256] + bias
// ---------------------------------------------------------------------------
template <int HEADMAJOR>
__global__ __launch_bounds__(256) void gemm256_kernel(
    const float* __restrict__ A, const float* __restrict__ W,
    const float* __restrict__ bias, float* __restrict__ out)
{
    __shared__ float As[16][68];
    __shared__ __align__(16) u64 Bs[16][32];

    const int t  = threadIdx.x;
    const int tx = t & 15;
    const int ty = t >> 4;
    const int c0 = blockIdx.x * 64;
    const int m0 = blockIdx.y * 64;

    u64 acc[4][2];
#pragma unroll
    for (int i = 0; i < 4; i++)
#pragma unroll
        for (int j = 0; j < 2; j++) acc[i][j] = pack2(0.f, 0.f);

    const int a_m  = t >> 2;
    const int a_k4 = (t & 3) * 4;
    const int b_k  = t >> 4;
    const int b_c4 = (t & 15) * 4;

    for (int k0 = 0; k0 < 256; k0 += 16) {
        float4 av = *(const float4*)&A[(size_t)(m0 + a_m) * 256 + k0 + a_k4];
        float4 wv = *(const float4*)&W[(size_t)(k0 + b_k) * 256 + c0 + b_c4];
        As[a_k4 + 0][a_m] = av.x;
        As[a_k4 + 1][a_m] = av.y;
        As[a_k4 + 2][a_m] = av.z;
        As[a_k4 + 3][a_m] = av.w;
        Bs[b_k][b_c4 / 2]     = pack2(wv.x, wv.y);
        Bs[b_k][b_c4 / 2 + 1] = pack2(wv.z, wv.w);
        __syncthreads();

#pragma unroll
        for (int k = 0; k < 16; k++) {
            float4 a = *(const float4*)&As[k][ty * 4];
            const ulonglong2 bb = *(const ulonglong2*)&Bs[k][tx * 2];
            u64 b0 = bb.x, b1 = bb.y;
            u64 a0 = pack2(a.x, a.x), a1 = pack2(a.y, a.y);
            u64 a2 = pack2(a.z, a.z), a3 = pack2(a.w, a.w);
            acc[0][0] = ffma2(a0, b0, acc[0][0]); acc[0][1] = ffma2(a0, b1, acc[0][1]);
            acc[1][0] = ffma2(a1, b0, acc[1][0]); acc[1][1] = ffma2(a1, b1, acc[1][1]);
            acc[2][0] = ffma2(a2, b0, acc[2][0]); acc[2][1] = ffma2(a2, b1, acc[2][1]);
            acc[3][0] = ffma2(a3, b0, acc[3][0]); acc[3][1] = ffma2(a3, b1, acc[3][1]);
        }
        __syncthreads();
    }

    const int c = c0 + tx * 4;
    float bv0 = bias[c], bv1 = bias[c + 1], bv2 = bias[c + 2], bv3 = bias[c + 3];

#pragma unroll
    for (int i = 0; i < 4; i++) {
        int m = m0 + ty * 4 + i;
        float l0, h0, l1, h1;
        unpack2(acc[i][0], l0, h0);
        unpack2(acc[i][1], l1, h1);
        float4 r = make_float4(l0 + bv0, h0 + bv1, l1 + bv2, h1 + bv3);
        if (HEADMAJOR) {
            int hh = c >> 5;
            int dh = c & 31;
            int b  = m / N_;
            int n  = m - b * N_;
            *(float4*)&out[(((size_t)(b * H_ + hh)) * N_ + n) * DH_ + dh] = r;
        } else {
            *(float4*)&out[(size_t)m * 256 + c] = r;
        }
    }
}

// ---------------------------------------------------------------------------
// mma.sync tf32 flash attention.
// CTA = 128 q-rows x 1 head; 4 warps, each owns 32 q-rows.
// SMEM: K/V double-buffered (strides 36/40 floats -> conflict-free frag LDS),
//       per-warp P buffer for C-frag -> A-frag layout conversion.
// ---------------------------------------------------------------------------
constexpr int NTILE = N_ / 128;   // 18

constexpr int KS_ST = 36;
constexpr int VS_ST = 40;
constexpr int PS_ST = 36;
constexpr int OFF_K0 = 0;
constexpr int OFF_K1 = 128 * KS_ST;                 // 4608
constexpr int OFF_V0 = 2 * 128 * KS_ST;             // 9216
constexpr int OFF_V1 = OFF_V0 + 128 * VS_ST;        // 14336
constexpr int OFF_P  = OFF_V0 + 2 * 128 * VS_ST;    // 19456
constexpr int SMEM_ATTN_FLOATS = OFF_P + 4 * 32 * PS_ST;  // 24064
constexpr int SMEM_ATTN_BYTES  = SMEM_ATTN_FLOATS * 4;    // 96256

__global__ __launch_bounds__(128) void attn_mma_kernel()
{
    extern __shared__ __align__(16) float smf[];
    const int tid  = threadIdx.x;
    const int warp = tid >> 5;
    const int lane = tid & 31;
    const int gid  = lane >> 2;    // groupID (0..7)
    const int tig  = lane & 3;     // thread-in-group (0..3)
    const int bh   = blockIdx.y;
    const int qt   = blockIdx.x;

    const float* Qg = g_q + ((size_t)bh * N_ + qt * 128) * DH_;
    const float* Kg = g_k + (size_t)bh * N_ * DH_;
    const float* Vg = g_v + (size_t)bh * N_ * DH_;

    // ---- Q fragments in registers (held for entire kernel) ----
    uint32_t qa[2][4][4];
#pragma unroll
    for (int m = 0; m < 2; m++) {
        const float* r0 = Qg + (size_t)(warp * 32 + m * 16 + gid) * DH_;
        const float* r1 = r0 + 8 * DH_;
#pragma unroll
        for (int ks = 0; ks < 4; ks++) {
            qa[m][ks][0] = tf32r(r0[ks * 8 + tig]);
            qa[m][ks][1] = tf32r(r1[ks * 8 + tig]);
            qa[m][ks][2] = tf32r(r0[ks * 8 + tig + 4]);
            qa[m][ks][3] = tf32r(r1[ks * 8 + tig + 4]);
        }
    }

    // ---- persistent accumulators ----
    float oacc[2][4][4];
#pragma unroll
    for (int m = 0; m < 2; m++)
#pragma unroll
        for (int n = 0; n < 4; n++)
#pragma unroll
            for (int r = 0; r < 4; r++) oacc[m][n][r] = 0.f;
    float lp[2][2] = {{0.f, 0.f}, {0.f, 0.f}};

    // exp2-folded softmax: p = 2^(s*CS2 - C2); the constant cancels in the divide.
    const float CS2 = 0.17677669529663687f * 1.4426950408889634f;
    const float C2  = 8.0f * 1.4426950408889634f;

    float* Pw = smf + OFF_P + warp * 32 * PS_ST;

    // ---- tile loader (gmem -> tf32-rounded SMEM) ----
    auto load_tile = [&](int t, int buf) {
        float* kd = smf + (buf ? OFF_K1 : OFF_K0);
        float* vd = smf + (buf ? OFF_V1 : OFF_V0);
        const float4* ks4 = (const float4*)(Kg + (size_t)t * 128 * DH_);
        const float4* vs4 = (const float4*)(Vg + (size_t)t * 128 * DH_);
#pragma unroll
        for (int i = tid; i < 1024; i += 128) {
            int key = i >> 3, c = i & 7;
            float4 kv = ks4[i];
            float4 vv = vs4[i];
            float4 kt, vt;
            kt.x = __uint_as_float(tf32r(kv.x));
            kt.y = __uint_as_float(tf32r(kv.y));
            kt.z = __uint_as_float(tf32r(kv.z));
            kt.w = __uint_as_float(tf32r(kv.w));
            vt.x = __uint_as_float(tf32r(vv.x));
            vt.y = __uint_as_float(tf32r(vv.y));
            vt.z = __uint_as_float(tf32r(vv.z));
            vt.w = __uint_as_float(tf32r(vv.w));
            *(float4*)(kd + key * KS_ST + c * 4) = kt;
            *(float4*)(vd + key * VS_ST + c * 4) = vt;
        }
    };

    load_tile(0, 0);
    __syncthreads();

    for (int t = 0; t < NTILE; t++) {
        const int buf = t & 1;
        if (t + 1 < NTILE) load_tile(t + 1, buf ^ 1);

        const float* Kb = smf + (buf ? OFF_K1 : OFF_K0);
        const float* Vb = smf + (buf ? OFF_V1 : OFF_V0);

#pragma unroll
        for (int chunk = 0; chunk < 4; chunk++) {
            const int kb = chunk * 32;

            // ---- S = Q K^T over 32 keys ----
            float s[2][4][4];
#pragma unroll
            for (int m = 0; m < 2; m++)
#pragma unroll
                for (int n = 0; n < 4; n++)
#pragma unroll
                    for (int r = 0; r < 4; r++) s[m][n][r] = 0.f;

#pragma unroll
            for (int ks = 0; ks < 4; ks++) {
#pragma unroll
                for (int n = 0; n < 4; n++) {
                    const float* kp = Kb + (size_t)(kb + n * 8 + gid) * KS_ST + ks * 8 + tig;
                    uint32_t b0 = fasu(kp[0]);
                    uint32_t b1 = fasu(kp[4]);
                    mma_tf32(s[0][n], qa[0][ks], b0, b1);
                    mma_tf32(s[1][n], qa[1][ks], b0, b1);
                }
            }

            // ---- softmax (fixed shift) + P store (C-frag -> SMEM) ----
#pragma unroll
            for (int m = 0; m < 2; m++) {
                float* pr0 = Pw + (size_t)(m * 16 + gid) * PS_ST;
                float* pr1 = pr0 + 8 * PS_ST;
#pragma unroll
                for (int n = 0; n < 4; n++) {
                    float p0 = ex2f(fmaf(s[m][n][0], CS2, -C2));
                    float p1 = ex2f(fmaf(s[m][n][1], CS2, -C2));
                    float p2 = ex2f(fmaf(s[m][n][2], CS2, -C2));
                    float p3 = ex2f(fmaf(s[m][n][3], CS2, -C2));
                    lp[m][0] += p0 + p1;
                    lp[m][1] += p2 + p3;
                    float2 w0, w1;
                    w0.x = __uint_as_float(tf32r(p0));
                    w0.y = __uint_as_float(tf32r(p1));
                    w1.x = __uint_as_float(tf32r(p2));
                    w1.y = __uint_as_float(tf32r(p3));
                    *(float2*)(pr0 + n * 8 + 2 * tig) = w0;
                    *(float2*)(pr1 + n * 8 + 2 * tig) = w1;
                }
            }
            __syncwarp();

            // ---- O += P V over these 32 keys ----
#pragma unroll
            for (int ks = 0; ks < 4; ks++) {
                uint32_t pa[2][4];
#pragma unroll
                for (int m = 0; m < 2; m++) {
                    const float* pp = Pw + (size_t)(m * 16 + gid) * PS_ST + ks * 8 + tig;
                    pa[m][0] = fasu(pp[0]);
                    pa[m][1] = fasu(pp[8 * PS_ST]);
                    pa[m][2] = fasu(pp[4]);
                    pa[m][3] = fasu(pp[8 * PS_ST + 4]);
                }
#pragma unroll
                for (int n = 0; n < 4; n++) {
                    const float* vp = Vb + (size_t)(kb + ks * 8 + tig) * VS_ST + n * 8 + gid;
                    uint32_t b0 = fasu(vp[0]);
                    uint32_t b1 = fasu(vp[4 * VS_ST]);
                    mma_tf32(oacc[0][n], pa[0], b0, b1);
                    mma_tf32(oacc[1][n], pa[1], b0, b1);
                }
            }
            __syncwarp();  // Pw reused next chunk
        }
        __syncthreads();   // everyone done with buf; prefetch of buf^1 complete
    }

    // ---- epilogue: row sums, divide, store ----
#pragma unroll
    for (int m = 0; m < 2; m++)
#pragma unroll
        for (int r = 0; r < 2; r++) {
            float v = lp[m][r];
            v += __shfl_xor_sync(0xFFFFFFFFu, v, 1);
            v += __shfl_xor_sync(0xFFFFFFFFu, v, 2);
            lp[m][r] = 1.0f / v;
        }

    const int b  = bh >> 3;
    const int hh = bh & 7;
#pragma unroll
    for (int m = 0; m < 2; m++) {
        int q0 = qt * 128 + warp * 32 + m * 16 + gid;
#pragma unroll
        for (int n = 0; n < 4; n++) {
            int col = hh * 32 + n * 8 + 2 * tig;
            float2 w0, w1;
            w0.x = oacc[m][n][0] * lp[m][0];
            w0.y = oacc[m][n][1] * lp[m][0];
            w1.x = oacc[m][n][2] * lp[m][1];
            w1.y = oacc[m][n][3] * lp[m][1];
            *(float2*)&g_ctx[(size_t)(b * N_ + q0) * D_ + col]       = w0;
            *(float2*)&g_ctx[(size_t)(b * N_ + q0 + 8) * D_ + col]   = w1;
        }
    }
}

// ---------------------------------------------------------------------------
extern "C" void kernel_launch(void* const* d_in, const int* in_sizes, int n_in,
                              void* d_out, int out_size)
{
    const float* x  = (const float*)d_in[0];
    const float* Wq = (const float*)d_in[1];
    const float* bq = (const float*)d_in[2];
    const float* Wk = (const float*)d_in[3];
    const float* bk = (const float*)d_in[4];
    const float* Wv = (const float*)d_in[5];
    const float* bv = (const float*)d_in[6];
    const float* Wo = (const float*)d_in[7];
    const float* bo = (const float*)d_in[8];
    float* out = (float*)d_out;

    float *qp, *kp, *vp, *ctxp;
    cudaGetSymbolAddress((void**)&qp,   g_q);
    cudaGetSymbolAddress((void**)&kp,   g_k);
    cudaGetSymbolAddress((void**)&vp,   g_v);
    cudaGetSymbolAddress((void**)&ctxp, g_ctx);

    cudaFuncSetAttribute(attn_mma_kernel,
                         cudaFuncAttributeMaxDynamicSharedMemorySize,
                         SMEM_ATTN_BYTES);

    dim3 ggrid(256 / 64, M_ / 64);   // (4, 72)
    dim3 gblk(256);

    gemm256_kernel<1><<<ggrid, gblk>>>(x, Wq, bq, qp);
    gemm256_kernel<1><<<ggrid, gblk>>>(x, Wk, bk, kp);
    gemm256_kernel<1><<<ggrid, gblk>>>(x, Wv, bv, vp);

    dim3 agrid(NTILE, BH_);          // (18, 16)
    attn_mma_kernel<<<agrid, 128, SMEM_ATTN_BYTES>>>();

    gemm256_kernel<0><<<ggrid, gblk>>>(ctxp, Wo, bo, out);
}

// round 5
// speedup vs baseline: 4.2656x; 1.4340x over previous
#include <cuda_runtime.h>
#include <cstdint>

// ---------------------------------------------------------------------------
// TriangularAttention: B=2, S=48 -> N=2304, D=256, H=8, DH=32
// Round 5: all GEMMs moved to mma.sync tf32 (QKV fused into one launch);
//          attention kernel unchanged from round 4 (94.8us, proven).
// ---------------------------------------------------------------------------

constexpr int B_  = 2;
constexpr int S_  = 48;
constexpr int D_  = 256;
constexpr int H_  = 8;
constexpr int DH_ = 32;
constexpr int N_  = S_ * S_;     // 2304
constexpr int M_  = B_ * N_;     // 4608
constexpr int BH_ = B_ * H_;     // 16

__device__ float g_q[BH_ * N_ * DH_];    // [b*H+h][n][dh]
__device__ float g_k[BH_ * N_ * DH_];
__device__ float g_v[BH_ * N_ * DH_];
__device__ float g_ctx[M_ * D_];         // [b*N+n][d]

// ---------------- mma.sync helpers -----------------------------------------
__device__ __forceinline__ uint32_t tf32r(float x) {   // round-to-nearest tf32
    uint32_t r;
    asm("cvt.rna.tf32.f32 %0, %1;" : "=r"(r) : "f"(x));
    return r;
}
__device__ __forceinline__ float ex2f(float x) {
    float y;
    asm("ex2.approx.ftz.f32 %0, %1;" : "=f"(y) : "f"(x));
    return y;
}
__device__ __forceinline__ void mma_tf32(float* d, const uint32_t* a,
                                         uint32_t b0, uint32_t b1) {
    asm volatile(
        "mma.sync.aligned.m16n8k8.row.col.f32.tf32.tf32.f32 "
        "{%0,%1,%2,%3}, {%4,%5,%6,%7}, {%8,%9}, {%0,%1,%2,%3};"
        : "+f"(d[0]), "+f"(d[1]), "+f"(d[2]), "+f"(d[3])
        : "r"(a[0]), "r"(a[1]), "r"(a[2]), "r"(a[3]), "r"(b0), "r"(b1));
}
__device__ __forceinline__ uint32_t fasu(float x) { return __float_as_uint(x); }

// ---------------------------------------------------------------------------
// Tensor-core GEMM: out[M,256] = A[M,256] @ W[256,256] + bias
// CTA tile 128x64, 256 threads (8 warps: 4 row x 2 col), k-chunks of 32,
// double-buffered SMEM. blockIdx.z selects (W, bias, out) triple.
// A staged tf32 at stride 36 (A-frag LDS bank = lane, conflict-free).
// W staged untransposed [k][c] at stride 72 (b-frag bank = 8*tig+gid, c.f.).
// ---------------------------------------------------------------------------
constexpr int GA_ST = 36;                       // A smem stride (floats)
constexpr int GW_ST = 72;                       // W smem stride (floats)
constexpr int GA_BUF = 128 * GA_ST;             // 4608 floats
constexpr int GW_BUF = 32 * GW_ST;              // 2304 floats
constexpr int GSM_BYTES = (2 * GA_BUF + 2 * GW_BUF) * 4;   // 55296

template <int HEADMAJOR>
__global__ __launch_bounds__(256) void gemm_mma_kernel(
    const float* __restrict__ A,
    const float* __restrict__ W0, const float* __restrict__ W1,
    const float* __restrict__ W2,
    const float* __restrict__ bias0, const float* __restrict__ bias1,
    const float* __restrict__ bias2,
    float* __restrict__ out0, float* __restrict__ out1,
    float* __restrict__ out2)
{
    extern __shared__ __align__(16) float sm[];

    const int z = blockIdx.z;
    const float* W    = (z == 0) ? W0 : (z == 1) ? W1 : W2;
    const float* bias = (z == 0) ? bias0 : (z == 1) ? bias1 : bias2;
    float* out        = (z == 0) ? out0 : (z == 1) ? out1 : out2;

    const int tid  = threadIdx.x;
    const int warp = tid >> 5;
    const int lane = tid & 31;
    const int gid  = lane >> 2;
    const int tig  = lane & 3;
    const int wr   = warp & 3;          // warp row (0..3) -> 32 rows
    const int wc   = warp >> 2;         // warp col (0..1) -> 32 cols
    const int c0   = blockIdx.x * 64;
    const int m0   = blockIdx.y * 128;

    float acc[2][4][4];
#pragma unroll
    for (int m = 0; m < 2; m++)
#pragma unroll
        for (int n = 0; n < 4; n++)
#pragma unroll
            for (int r = 0; r < 4; r++) acc[m][n][r] = 0.f;

    auto load_chunk = [&](int k0, int buf) {
        float* as = sm + buf * GA_BUF;
        float* ws = sm + 2 * GA_BUF + buf * GW_BUF;
        // A chunk: 128 rows x 32 k = 1024 float4 (4 per thread), tf32-rounded
#pragma unroll
        for (int r = 0; r < 4; r++) {
            int idx = tid + r * 256;
            int row = idx >> 3, c4 = idx & 7;
            float4 v = *(const float4*)&A[(size_t)(m0 + row) * 256 + k0 + c4 * 4];
            float4 tv;
            tv.x = __uint_as_float(tf32r(v.x));
            tv.y = __uint_as_float(tf32r(v.y));
            tv.z = __uint_as_float(tf32r(v.z));
            tv.w = __uint_as_float(tf32r(v.w));
            *(float4*)&as[row * GA_ST + c4 * 4] = tv;
        }
        // W chunk: 32 k x 64 c = 512 float4 (2 per thread), kept [k][c]
#pragma unroll
        for (int r = 0; r < 2; r++) {
            int idx = tid + r * 256;
            int kk = idx >> 4, c4 = idx & 15;
            float4 v = *(const float4*)&W[(size_t)(k0 + kk) * 256 + c0 + c4 * 4];
            float4 tv;
            tv.x = __uint_as_float(tf32r(v.x));
            tv.y = __uint_as_float(tf32r(v.y));
            tv.z = __uint_as_float(tf32r(v.z));
            tv.w = __uint_as_float(tf32r(v.w));
            *(float4*)&ws[kk * GW_ST + c4 * 4] = tv;
        }
    };

    load_chunk(0, 0);
    __syncthreads();

#pragma unroll 1
    for (int kc = 0; kc < 8; kc++) {
        const int buf = kc & 1;
        if (kc + 1 < 8) load_chunk((kc + 1) * 32, buf ^ 1);

        const float* as = sm + buf * GA_BUF;
        const float* ws = sm + 2 * GA_BUF + buf * GW_BUF;

#pragma unroll
        for (int ks = 0; ks < 4; ks++) {
            uint32_t a[2][4];
#pragma unroll
            for (int m = 0; m < 2; m++) {
                const float* ap = as + (size_t)(wr * 32 + m * 16 + gid) * GA_ST
                                + ks * 8 + tig;
                a[m][0] = fasu(ap[0]);
                a[m][1] = fasu(ap[8 * GA_ST]);
                a[m][2] = fasu(ap[4]);
                a[m][3] = fasu(ap[8 * GA_ST + 4]);
            }
#pragma unroll
            for (int n = 0; n < 4; n++) {
                // b-frag: B[n][k] = W[k][c]^T -> read Ws[k = ks*8+tig][c = wc*32+n*8+gid]
                const float* bp = ws + (size_t)(ks * 8 + tig) * GW_ST
                                + wc * 32 + n * 8 + gid;
                uint32_t b0 = fasu(bp[0]);
                uint32_t b1 = fasu(bp[4 * GW_ST]);
                mma_tf32(acc[0][n], a[0], b0, b1);
                mma_tf32(acc[1][n], a[1], b0, b1);
            }
        }
        __syncthreads();
    }

    // Epilogue: +bias, store
#pragma unroll
    for (int n = 0; n < 4; n++) {
        int c = c0 + wc * 32 + n * 8 + 2 * tig;
        float bv0 = bias[c], bv1 = bias[c + 1];
#pragma unroll
        for (int m = 0; m < 2; m++) {
            int row = m0 + wr * 32 + m * 16 + gid;
            float2 w0 = make_float2(acc[m][n][0] + bv0, acc[m][n][1] + bv1);
            float2 w1 = make_float2(acc[m][n][2] + bv0, acc[m][n][3] + bv1);
            if (HEADMAJOR) {
                int hh = c >> 5;
                int dh = c & 31;
                int b  = row / N_;
                int nn = row - b * N_;
                float* p = out + (((size_t)(b * H_ + hh)) * N_ + nn) * DH_ + dh;
                *(float2*)p              = w0;
                *(float2*)(p + 8 * DH_)  = w1;
            } else {
                float* p = out + (size_t)row * 256 + c;
                *(float2*)p              = w0;
                *(float2*)(p + 8 * 256)  = w1;
            }
        }
    }
}

// ---------------------------------------------------------------------------
// mma.sync tf32 flash attention (unchanged from round 4).
// ---------------------------------------------------------------------------
constexpr int NTILE = N_ / 128;   // 18

constexpr int KS_ST = 36;
constexpr int VS_ST = 40;
constexpr int PS_ST = 36;
constexpr int OFF_K0 = 0;
constexpr int OFF_K1 = 128 * KS_ST;
constexpr int OFF_V0 = 2 * 128 * KS_ST;
constexpr int OFF_V1 = OFF_V0 + 128 * VS_ST;
constexpr int OFF_P  = OFF_V0 + 2 * 128 * VS_ST;
constexpr int SMEM_ATTN_FLOATS = OFF_P + 4 * 32 * PS_ST;
constexpr int SMEM_ATTN_BYTES  = SMEM_ATTN_FLOATS * 4;    // 96256

__global__ __launch_bounds__(128) void attn_mma_kernel()
{
    extern __shared__ __align__(16) float smf[];
    const int tid  = threadIdx.x;
    const int warp = tid >> 5;
    const int lane = tid & 31;
    const int gid  = lane >> 2;
    const int tig  = lane & 3;
    const int bh   = blockIdx.y;
    const int qt   = blockIdx.x;

    const float* Qg = g_q + ((size_t)bh * N_ + qt * 128) * DH_;
    const float* Kg = g_k + (size_t)bh * N_ * DH_;
    const float* Vg = g_v + (size_t)bh * N_ * DH_;

    uint32_t qa[2][4][4];
#pragma unroll
    for (int m = 0; m < 2; m++) {
        const float* r0 = Qg + (size_t)(warp * 32 + m * 16 + gid) * DH_;
        const float* r1 = r0 + 8 * DH_;
#pragma unroll
        for (int ks = 0; ks < 4; ks++) {
            qa[m][ks][0] = tf32r(r0[ks * 8 + tig]);
            qa[m][ks][1] = tf32r(r1[ks * 8 + tig]);
            qa[m][ks][2] = tf32r(r0[ks * 8 + tig + 4]);
            qa[m][ks][3] = tf32r(r1[ks * 8 + tig + 4]);
        }
    }

    float oacc[2][4][4];
#pragma unroll
    for (int m = 0; m < 2; m++)
#pragma unroll
        for (int n = 0; n < 4; n++)
#pragma unroll
            for (int r = 0; r < 4; r++) oacc[m][n][r] = 0.f;
    float lp[2][2] = {{0.f, 0.f}, {0.f, 0.f}};

    const float CS2 = 0.17677669529663687f * 1.4426950408889634f;
    const float C2  = 8.0f * 1.4426950408889634f;

    float* Pw = smf + OFF_P + warp * 32 * PS_ST;

    auto load_tile = [&](int t, int buf) {
        float* kd = smf + (buf ? OFF_K1 : OFF_K0);
        float* vd = smf + (buf ? OFF_V1 : OFF_V0);
        const float4* ks4 = (const float4*)(Kg + (size_t)t * 128 * DH_);
        const float4* vs4 = (const float4*)(Vg + (size_t)t * 128 * DH_);
#pragma unroll
        for (int i = tid; i < 1024; i += 128) {
            int key = i >> 3, c = i & 7;
            float4 kv = ks4[i];
            float4 vv = vs4[i];
            float4 kt, vt;
            kt.x = __uint_as_float(tf32r(kv.x));
            kt.y = __uint_as_float(tf32r(kv.y));
            kt.z = __uint_as_float(tf32r(kv.z));
            kt.w = __uint_as_float(tf32r(kv.w));
            vt.x = __uint_as_float(tf32r(vv.x));
            vt.y = __uint_as_float(tf32r(vv.y));
            vt.z = __uint_as_float(tf32r(vv.z));
            vt.w = __uint_as_float(tf32r(vv.w));
            *(float4*)(kd + key * KS_ST + c * 4) = kt;
            *(float4*)(vd + key * VS_ST + c * 4) = vt;
        }
    };

    load_tile(0, 0);
    __syncthreads();

    for (int t = 0; t < NTILE; t++) {
        const int buf = t & 1;
        if (t + 1 < NTILE) load_tile(t + 1, buf ^ 1);

        const float* Kb = smf + (buf ? OFF_K1 : OFF_K0);
        const float* Vb = smf + (buf ? OFF_V1 : OFF_V0);

#pragma unroll
        for (int chunk = 0; chunk < 4; chunk++) {
            const int kb = chunk * 32;

            float s[2][4][4];
#pragma unroll
            for (int m = 0; m < 2; m++)
#pragma unroll
                for (int n = 0; n < 4; n++)
#pragma unroll
                    for (int r = 0; r < 4; r++) s[m][n][r] = 0.f;

#pragma unroll
            for (int ks = 0; ks < 4; ks++) {
#pragma unroll
                for (int n = 0; n < 4; n++) {
                    const float* kp = Kb + (size_t)(kb + n * 8 + gid) * KS_ST + ks * 8 + tig;
                    uint32_t b0 = fasu(kp[0]);
                    uint32_t b1 = fasu(kp[4]);
                    mma_tf32(s[0][n], qa[0][ks], b0, b1);
                    mma_tf32(s[1][n], qa[1][ks], b0, b1);
                }
            }

#pragma unroll
            for (int m = 0; m < 2; m++) {
                float* pr0 = Pw + (size_t)(m * 16 + gid) * PS_ST;
                float* pr1 = pr0 + 8 * PS_ST;
#pragma unroll
                for (int n = 0; n < 4; n++) {
                    float p0 = ex2f(fmaf(s[m][n][0], CS2, -C2));
                    float p1 = ex2f(fmaf(s[m][n][1], CS2, -C2));
                    float p2 = ex2f(fmaf(s[m][n][2], CS2, -C2));
                    float p3 = ex2f(fmaf(s[m][n][3], CS2, -C2));
                    lp[m][0] += p0 + p1;
                    lp[m][1] += p2 + p3;
                    float2 w0, w1;
                    w0.x = __uint_as_float(tf32r(p0));
                    w0.y = __uint_as_float(tf32r(p1));
                    w1.x = __uint_as_float(tf32r(p2));
                    w1.y = __uint_as_float(tf32r(p3));
                    *(float2*)(pr0 + n * 8 + 2 * tig) = w0;
                    *(float2*)(pr1 + n * 8 + 2 * tig) = w1;
                }
            }
            __syncwarp();

#pragma unroll
            for (int ks = 0; ks < 4; ks++) {
                uint32_t pa[2][4];
#pragma unroll
                for (int m = 0; m < 2; m++) {
                    const float* pp = Pw + (size_t)(m * 16 + gid) * PS_ST + ks * 8 + tig;
                    pa[m][0] = fasu(pp[0]);
                    pa[m][1] = fasu(pp[8 * PS_ST]);
                    pa[m][2] = fasu(pp[4]);
                    pa[m][3] = fasu(pp[8 * PS_ST + 4]);
                }
#pragma unroll
                for (int n = 0; n < 4; n++) {
                    const float* vp = Vb + (size_t)(kb + ks * 8 + tig) * VS_ST + n * 8 + gid;
                    uint32_t b0 = fasu(vp[0]);
                    uint32_t b1 = fasu(vp[4 * VS_ST]);
                    mma_tf32(oacc[0][n], pa[0], b0, b1);
                    mma_tf32(oacc[1][n], pa[1], b0, b1);
                }
            }
            __syncwarp();
        }
        __syncthreads();
    }

#pragma unroll
    for (int m = 0; m < 2; m++)
#pragma unroll
        for (int r = 0; r < 2; r++) {
            float v = lp[m][r];
            v += __shfl_xor_sync(0xFFFFFFFFu, v, 1);
            v += __shfl_xor_sync(0xFFFFFFFFu, v, 2);
            lp[m][r] = 1.0f / v;
        }

    const int b  = bh >> 3;
    const int hh = bh & 7;
#pragma unroll
    for (int m = 0; m < 2; m++) {
        int q0 = qt * 128 + warp * 32 + m * 16 + gid;
#pragma unroll
        for (int n = 0; n < 4; n++) {
            int col = hh * 32 + n * 8 + 2 * tig;
            float2 w0, w1;
            w0.x = oacc[m][n][0] * lp[m][0];
            w0.y = oacc[m][n][1] * lp[m][0];
            w1.x = oacc[m][n][2] * lp[m][1];
            w1.y = oacc[m][n][3] * lp[m][1];
            *(float2*)&g_ctx[(size_t)(b * N_ + q0) * D_ + col]       = w0;
            *(float2*)&g_ctx[(size_t)(b * N_ + q0 + 8) * D_ + col]   = w1;
        }
    }
}

// ---------------------------------------------------------------------------
extern "C" void kernel_launch(void* const* d_in, const int* in_sizes, int n_in,
                              void* d_out, int out_size)
{
    const float* x  = (const float*)d_in[0];
    const float* Wq = (const float*)d_in[1];
    const float* bq = (const float*)d_in[2];
    const float* Wk = (const float*)d_in[3];
    const float* bk = (const float*)d_in[4];
    const float* Wv = (const float*)d_in[5];
    const float* bv = (const float*)d_in[6];
    const float* Wo = (const float*)d_in[7];
    const float* bo = (const float*)d_in[8];
    float* out = (float*)d_out;

    float *qp, *kp, *vp, *ctxp;
    cudaGetSymbolAddress((void**)&qp,   g_q);
    cudaGetSymbolAddress((void**)&kp,   g_k);
    cudaGetSymbolAddress((void**)&vp,   g_v);
    cudaGetSymbolAddress((void**)&ctxp, g_ctx);

    cudaFuncSetAttribute(gemm_mma_kernel<1>,
                         cudaFuncAttributeMaxDynamicSharedMemorySize, GSM_BYTES);
    cudaFuncSetAttribute(gemm_mma_kernel<0>,
                         cudaFuncAttributeMaxDynamicSharedMemorySize, GSM_BYTES);
    cudaFuncSetAttribute(attn_mma_kernel,
                         cudaFuncAttributeMaxDynamicSharedMemorySize,
                         SMEM_ATTN_BYTES);

    // Fused Q/K/V projections: grid.z selects the matrix.
    dim3 qkv_grid(256 / 64, M_ / 128, 3);    // (4, 36, 3)
    gemm_mma_kernel<1><<<qkv_grid, 256, GSM_BYTES>>>(
        x, Wq, Wk, Wv, bq, bk, bv, qp, kp, vp);

    dim3 agrid(NTILE, BH_);                  // (18, 16)
    attn_mma_kernel<<<agrid, 128, SMEM_ATTN_BYTES>>>();

    dim3 o_grid(256 / 64, M_ / 128, 1);      // (4, 36, 1)
    gemm_mma_kernel<0><<<o_grid, 256, GSM_BYTES>>>(
        ctxp, Wo, Wo, Wo, bo, bo, bo, out, out, out);
}

// round 6
// speedup vs baseline: 4.3413x; 1.0177x over previous
#include <cuda_runtime.h>
#include <cstdint>

// ---------------------------------------------------------------------------
// TriangularAttention: B=2, S=48 -> N=2304, D=256, H=8, DH=32
// Round 6: attention rebuilt with 8 warps/CTA (key-split, linear softmax),
//          shfl-based P transpose (no P SMEM), V0-buffer reused for combine.
//          GEMMs unchanged from round 5.
// ---------------------------------------------------------------------------

constexpr int B_  = 2;
constexpr int S_  = 48;
constexpr int D_  = 256;
constexpr int H_  = 8;
constexpr int DH_ = 32;
constexpr int N_  = S_ * S_;     // 2304
constexpr int M_  = B_ * N_;     // 4608
constexpr int BH_ = B_ * H_;     // 16

__device__ float g_q[BH_ * N_ * DH_];    // [b*H+h][n][dh]
__device__ float g_k[BH_ * N_ * DH_];
__device__ float g_v[BH_ * N_ * DH_];
__device__ float g_ctx[M_ * D_];         // [b*N+n][d]

// ---------------- mma.sync helpers -----------------------------------------
__device__ __forceinline__ uint32_t tf32r(float x) {   // round-to-nearest tf32
    uint32_t r;
    asm("cvt.rna.tf32.f32 %0, %1;" : "=r"(r) : "f"(x));
    return r;
}
__device__ __forceinline__ float ex2f(float x) {
    float y;
    asm("ex2.approx.ftz.f32 %0, %1;" : "=f"(y) : "f"(x));
    return y;
}
__device__ __forceinline__ void mma_tf32(float* d, const uint32_t* a,
                                         uint32_t b0, uint32_t b1) {
    asm volatile(
        "mma.sync.aligned.m16n8k8.row.col.f32.tf32.tf32.f32 "
        "{%0,%1,%2,%3}, {%4,%5,%6,%7}, {%8,%9}, {%0,%1,%2,%3};"
        : "+f"(d[0]), "+f"(d[1]), "+f"(d[2]), "+f"(d[3])
        : "r"(a[0]), "r"(a[1]), "r"(a[2]), "r"(a[3]), "r"(b0), "r"(b1));
}
__device__ __forceinline__ uint32_t fasu(float x) { return __float_as_uint(x); }

// ---------------------------------------------------------------------------
// Tensor-core GEMM (unchanged from round 5): out[M,256] = A @ W + bias
// ---------------------------------------------------------------------------
constexpr int GA_ST = 36;
constexpr int GW_ST = 72;
constexpr int GA_BUF = 128 * GA_ST;
constexpr int GW_BUF = 32 * GW_ST;
constexpr int GSM_BYTES = (2 * GA_BUF + 2 * GW_BUF) * 4;   // 55296

template <int HEADMAJOR>
__global__ __launch_bounds__(256) void gemm_mma_kernel(
    const float* __restrict__ A,
    const float* __restrict__ W0, const float* __restrict__ W1,
    const float* __restrict__ W2,
    const float* __restrict__ bias0, const float* __restrict__ bias1,
    const float* __restrict__ bias2,
    float* __restrict__ out0, float* __restrict__ out1,
    float* __restrict__ out2)
{
    extern __shared__ __align__(16) float sm[];

    const int z = blockIdx.z;
    const float* W    = (z == 0) ? W0 : (z == 1) ? W1 : W2;
    const float* bias = (z == 0) ? bias0 : (z == 1) ? bias1 : bias2;
    float* out        = (z == 0) ? out0 : (z == 1) ? out1 : out2;

    const int tid  = threadIdx.x;
    const int warp = tid >> 5;
    const int lane = tid & 31;
    const int gid  = lane >> 2;
    const int tig  = lane & 3;
    const int wr   = warp & 3;
    const int wc   = warp >> 2;
    const int c0   = blockIdx.x * 64;
    const int m0   = blockIdx.y * 128;

    float acc[2][4][4];
#pragma unroll
    for (int m = 0; m < 2; m++)
#pragma unroll
        for (int n = 0; n < 4; n++)
#pragma unroll
            for (int r = 0; r < 4; r++) acc[m][n][r] = 0.f;

    auto load_chunk = [&](int k0, int buf) {
        float* as = sm + buf * GA_BUF;
        float* ws = sm + 2 * GA_BUF + buf * GW_BUF;
#pragma unroll
        for (int r = 0; r < 4; r++) {
            int idx = tid + r * 256;
            int row = idx >> 3, c4 = idx & 7;
            float4 v = *(const float4*)&A[(size_t)(m0 + row) * 256 + k0 + c4 * 4];
            float4 tv;
            tv.x = __uint_as_float(tf32r(v.x));
            tv.y = __uint_as_float(tf32r(v.y));
            tv.z = __uint_as_float(tf32r(v.z));
            tv.w = __uint_as_float(tf32r(v.w));
            *(float4*)&as[row * GA_ST + c4 * 4] = tv;
        }
#pragma unroll
        for (int r = 0; r < 2; r++) {
            int idx = tid + r * 256;
            int kk = idx >> 4, c4 = idx & 15;
            float4 v = *(const float4*)&W[(size_t)(k0 + kk) * 256 + c0 + c4 * 4];
            float4 tv;
            tv.x = __uint_as_float(tf32r(v.x));
            tv.y = __uint_as_float(tf32r(v.y));
            tv.z = __uint_as_float(tf32r(v.z));
            tv.w = __uint_as_float(tf32r(v.w));
            *(float4*)&ws[kk * GW_ST + c4 * 4] = tv;
        }
    };

    load_chunk(0, 0);
    __syncthreads();

#pragma unroll 1
    for (int kc = 0; kc < 8; kc++) {
        const int buf = kc & 1;
        if (kc + 1 < 8) load_chunk((kc + 1) * 32, buf ^ 1);

        const float* as = sm + buf * GA_BUF;
        const float* ws = sm + 2 * GA_BUF + buf * GW_BUF;

#pragma unroll
        for (int ks = 0; ks < 4; ks++) {
            uint32_t a[2][4];
#pragma unroll
            for (int m = 0; m < 2; m++) {
                const float* ap = as + (size_t)(wr * 32 + m * 16 + gid) * GA_ST
                                + ks * 8 + tig;
                a[m][0] = fasu(ap[0]);
                a[m][1] = fasu(ap[8 * GA_ST]);
                a[m][2] = fasu(ap[4]);
                a[m][3] = fasu(ap[8 * GA_ST + 4]);
            }
#pragma unroll
            for (int n = 0; n < 4; n++) {
                const float* bp = ws + (size_t)(ks * 8 + tig) * GW_ST
                                + wc * 32 + n * 8 + gid;
                uint32_t b0 = fasu(bp[0]);
                uint32_t b1 = fasu(bp[4 * GW_ST]);
                mma_tf32(acc[0][n], a[0], b0, b1);
                mma_tf32(acc[1][n], a[1], b0, b1);
            }
        }
        __syncthreads();
    }

#pragma unroll
    for (int n = 0; n < 4; n++) {
        int c = c0 + wc * 32 + n * 8 + 2 * tig;
        float bv0 = bias[c], bv1 = bias[c + 1];
#pragma unroll
        for (int m = 0; m < 2; m++) {
            int row = m0 + wr * 32 + m * 16 + gid;
            float2 w0 = make_float2(acc[m][n][0] + bv0, acc[m][n][1] + bv1);
            float2 w1 = make_float2(acc[m][n][2] + bv0, acc[m][n][3] + bv1);
            if (HEADMAJOR) {
                int hh = c >> 5;
                int dh = c & 31;
                int b  = row / N_;
                int nn = row - b * N_;
                float* p = out + (((size_t)(b * H_ + hh)) * N_ + nn) * DH_ + dh;
                *(float2*)p              = w0;
                *(float2*)(p + 8 * DH_)  = w1;
            } else {
                float* p = out + (size_t)row * 256 + c;
                *(float2*)p              = w0;
                *(float2*)(p + 8 * 256)  = w1;
            }
        }
    }
}

// ---------------------------------------------------------------------------
// mma.sync tf32 flash attention, 8 warps/CTA with key-split.
// warp = (wq, wk): wq = warp&3 owns q-rows [32wq,32wq+32);
//                  wk = warp>>2 owns keys [64wk, 64wk+64) of each 128-key tile.
// Linear (fixed-shift) softmax => partial (sum p, sum p*V) add at the end.
// P transpose C-frag -> A-frag via quad shfl (no SMEM P buffer).
// ---------------------------------------------------------------------------
constexpr int NTILE = N_ / 128;   // 18

constexpr int KS_ST = 36;
constexpr int VS_ST = 40;
constexpr int OFF_K0 = 0;
constexpr int OFF_K1 = 128 * KS_ST;                 // 4608
constexpr int OFF_V0 = 2 * 128 * KS_ST;             // 9216
constexpr int OFF_V1 = OFF_V0 + 128 * VS_ST;        // 14336
constexpr int SMEM_ATTN_FLOATS = OFF_V1 + 128 * VS_ST;  // 19456
constexpr int SMEM_ATTN_BYTES  = SMEM_ATTN_FLOATS * 4;  // 77824

__global__ __launch_bounds__(256, 2) void attn_mma_kernel()
{
    extern __shared__ __align__(16) float smf[];
    const int tid  = threadIdx.x;
    const int warp = tid >> 5;
    const int lane = tid & 31;
    const int gid  = lane >> 2;
    const int tig  = lane & 3;
    const int wq   = warp & 3;
    const int wk   = warp >> 2;
    const int bh   = blockIdx.y;
    const int qt   = blockIdx.x;

    const float* Qg = g_q + ((size_t)bh * N_ + qt * 128) * DH_;
    const float* Kg = g_k + (size_t)bh * N_ * DH_;
    const float* Vg = g_v + (size_t)bh * N_ * DH_;

    // ---- Q fragments in registers ----
    uint32_t qa[2][4][4];
#pragma unroll
    for (int m = 0; m < 2; m++) {
        const float* r0 = Qg + (size_t)(wq * 32 + m * 16 + gid) * DH_;
        const float* r1 = r0 + 8 * DH_;
#pragma unroll
        for (int ks = 0; ks < 4; ks++) {
            qa[m][ks][0] = tf32r(r0[ks * 8 + tig]);
            qa[m][ks][1] = tf32r(r1[ks * 8 + tig]);
            qa[m][ks][2] = tf32r(r0[ks * 8 + tig + 4]);
            qa[m][ks][3] = tf32r(r1[ks * 8 + tig + 4]);
        }
    }

    float oacc[2][4][4];
#pragma unroll
    for (int m = 0; m < 2; m++)
#pragma unroll
        for (int n = 0; n < 4; n++)
#pragma unroll
            for (int r = 0; r < 4; r++) oacc[m][n][r] = 0.f;
    float lp[2][2] = {{0.f, 0.f}, {0.f, 0.f}};

    const float CS2 = 0.17677669529663687f * 1.4426950408889634f;
    const float C2  = 8.0f * 1.4426950408889634f;

    const int lane_lo = (lane & 28) | (tig >> 1);
    const int lane_hi = lane_lo | 2;
    const bool sel    = tig & 1;

    auto load_tile = [&](int t, int buf) {
        float* kd = smf + (buf ? OFF_K1 : OFF_K0);
        float* vd = smf + (buf ? OFF_V1 : OFF_V0);
        const float4* ks4 = (const float4*)(Kg + (size_t)t * 128 * DH_);
        const float4* vs4 = (const float4*)(Vg + (size_t)t * 128 * DH_);
#pragma unroll
        for (int i = tid; i < 1024; i += 256) {
            int key = i >> 3, c = i & 7;
            float4 kv = ks4[i];
            float4 vv = vs4[i];
            float4 kt, vt;
            kt.x = __uint_as_float(tf32r(kv.x));
            kt.y = __uint_as_float(tf32r(kv.y));
            kt.z = __uint_as_float(tf32r(kv.z));
            kt.w = __uint_as_float(tf32r(kv.w));
            vt.x = __uint_as_float(tf32r(vv.x));
            vt.y = __uint_as_float(tf32r(vv.y));
            vt.z = __uint_as_float(tf32r(vv.z));
            vt.w = __uint_as_float(tf32r(vv.w));
            *(float4*)(kd + key * KS_ST + c * 4) = kt;
            *(float4*)(vd + key * VS_ST + c * 4) = vt;
        }
    };

    load_tile(0, 0);
    __syncthreads();

    for (int t = 0; t < NTILE; t++) {
        const int buf = t & 1;
        if (t + 1 < NTILE) load_tile(t + 1, buf ^ 1);

        const float* Kb = smf + (buf ? OFF_K1 : OFF_K0);
        const float* Vb = smf + (buf ? OFF_V1 : OFF_V0);

        // each warp-half covers 4 groups of 16 keys
#pragma unroll
        for (int g = 0; g < 4; g++) {
            const int kb = wk * 64 + g * 16;

            // ---- S = Q K^T over 16 keys (2 n-frags) ----
            float s[2][2][4];
#pragma unroll
            for (int m = 0; m < 2; m++)
#pragma unroll
                for (int n = 0; n < 2; n++)
#pragma unroll
                    for (int r = 0; r < 4; r++) s[m][n][r] = 0.f;

#pragma unroll
            for (int ks = 0; ks < 4; ks++) {
#pragma unroll
                for (int n = 0; n < 2; n++) {
                    const float* kp = Kb + (size_t)(kb + n * 8 + gid) * KS_ST + ks * 8 + tig;
                    uint32_t b0 = fasu(kp[0]);
                    uint32_t b1 = fasu(kp[4]);
                    mma_tf32(s[0][n], qa[0][ks], b0, b1);
                    mma_tf32(s[1][n], qa[1][ks], b0, b1);
                }
            }

            // ---- softmax + shfl transpose + PV, per 8-key step ----
#pragma unroll
            for (int kp2 = 0; kp2 < 2; kp2++) {
                uint32_t pa[2][4];
#pragma unroll
                for (int m = 0; m < 2; m++) {
                    float p0 = ex2f(fmaf(s[m][kp2][0], CS2, -C2));
                    float p1 = ex2f(fmaf(s[m][kp2][1], CS2, -C2));
                    float p2 = ex2f(fmaf(s[m][kp2][2], CS2, -C2));
                    float p3 = ex2f(fmaf(s[m][kp2][3], CS2, -C2));
                    lp[m][0] += p0 + p1;
                    lp[m][1] += p2 + p3;
                    uint32_t r0 = tf32r(p0), r1 = tf32r(p1);
                    uint32_t r2 = tf32r(p2), r3 = tf32r(p3);
                    uint32_t v00 = __shfl_sync(0xFFFFFFFFu, r0, lane_lo);
                    uint32_t v01 = __shfl_sync(0xFFFFFFFFu, r1, lane_lo);
                    uint32_t v02 = __shfl_sync(0xFFFFFFFFu, r2, lane_lo);
                    uint32_t v03 = __shfl_sync(0xFFFFFFFFu, r3, lane_lo);
                    uint32_t v10 = __shfl_sync(0xFFFFFFFFu, r0, lane_hi);
                    uint32_t v11 = __shfl_sync(0xFFFFFFFFu, r1, lane_hi);
                    uint32_t v12 = __shfl_sync(0xFFFFFFFFu, r2, lane_hi);
                    uint32_t v13 = __shfl_sync(0xFFFFFFFFu, r3, lane_hi);
                    pa[m][0] = sel ? v01 : v00;
                    pa[m][1] = sel ? v03 : v02;
                    pa[m][2] = sel ? v11 : v10;
                    pa[m][3] = sel ? v13 : v12;
                }
                const int krow = kb + kp2 * 8 + tig;
#pragma unroll
                for (int n = 0; n < 4; n++) {
                    const float* vp = Vb + (size_t)krow * VS_ST + n * 8 + gid;
                    uint32_t b0 = fasu(vp[0]);
                    uint32_t b1 = fasu(vp[4 * VS_ST]);
                    mma_tf32(oacc[0][n], pa[0], b0, b1);
                    mma_tf32(oacc[1][n], pa[1], b0, b1);
                }
            }
        }
        __syncthreads();
    }

    // ---- combine the two key-halves via SMEM (V0 region is dead now) ----
    float* sc = smf + OFF_V0 + wq * 1152;
    if (wk == 1) {
        int idx = 0;
#pragma unroll
        for (int m = 0; m < 2; m++)
#pragma unroll
            for (int n = 0; n < 4; n++)
#pragma unroll
                for (int r = 0; r < 4; r++)
                    sc[(idx++) * 32 + lane] = oacc[m][n][r];
#pragma unroll
        for (int m = 0; m < 2; m++)
#pragma unroll
            for (int r = 0; r < 2; r++)
                sc[1024 + (m * 2 + r) * 32 + lane] = lp[m][r];
    }
    __syncthreads();
    if (wk == 0) {
        int idx = 0;
#pragma unroll
        for (int m = 0; m < 2; m++)
#pragma unroll
            for (int n = 0; n < 4; n++)
#pragma unroll
                for (int r = 0; r < 4; r++)
                    oacc[m][n][r] += sc[(idx++) * 32 + lane];
#pragma unroll
        for (int m = 0; m < 2; m++)
#pragma unroll
            for (int r = 0; r < 2; r++)
                lp[m][r] += sc[1024 + (m * 2 + r) * 32 + lane];

        // row sums over the quad, invert
#pragma unroll
        for (int m = 0; m < 2; m++)
#pragma unroll
            for (int r = 0; r < 2; r++) {
                float v = lp[m][r];
                v += __shfl_xor_sync(0xFFFFFFFFu, v, 1);
                v += __shfl_xor_sync(0xFFFFFFFFu, v, 2);
                lp[m][r] = 1.0f / v;
            }

        const int b  = bh >> 3;
        const int hh = bh & 7;
#pragma unroll
        for (int m = 0; m < 2; m++) {
            int q0 = qt * 128 + wq * 32 + m * 16 + gid;
#pragma unroll
            for (int n = 0; n < 4; n++) {
                int col = hh * 32 + n * 8 + 2 * tig;
                float2 w0, w1;
                w0.x = oacc[m][n][0] * lp[m][0];
                w0.y = oacc[m][n][1] * lp[m][0];
                w1.x = oacc[m][n][2] * lp[m][1];
                w1.y = oacc[m][n][3] * lp[m][1];
                *(float2*)&g_ctx[(size_t)(b * N_ + q0) * D_ + col]     = w0;
                *(float2*)&g_ctx[(size_t)(b * N_ + q0 + 8) * D_ + col] = w1;
            }
        }
    }
}

// ---------------------------------------------------------------------------
extern "C" void kernel_launch(void* const* d_in, const int* in_sizes, int n_in,
                              void* d_out, int out_size)
{
    const float* x  = (const float*)d_in[0];
    const float* Wq = (const float*)d_in[1];
    const float* bq = (const float*)d_in[2];
    const float* Wk = (const float*)d_in[3];
    const float* bk = (const float*)d_in[4];
    const float* Wv = (const float*)d_in[5];
    const float* bv = (const float*)d_in[6];
    const float* Wo = (const float*)d_in[7];
    const float* bo = (const float*)d_in[8];
    float* out = (float*)d_out;

    float *qp, *kp, *vp, *ctxp;
    cudaGetSymbolAddress((void**)&qp,   g_q);
    cudaGetSymbolAddress((void**)&kp,   g_k);
    cudaGetSymbolAddress((void**)&vp,   g_v);
    cudaGetSymbolAddress((void**)&ctxp, g_ctx);

    cudaFuncSetAttribute(gemm_mma_kernel<1>,
                         cudaFuncAttributeMaxDynamicSharedMemorySize, GSM_BYTES);
    cudaFuncSetAttribute(gemm_mma_kernel<0>,
                         cudaFuncAttributeMaxDynamicSharedMemorySize, GSM_BYTES);
    cudaFuncSetAttribute(attn_mma_kernel,
                         cudaFuncAttributeMaxDynamicSharedMemorySize,
                         SMEM_ATTN_BYTES);

    dim3 qkv_grid(256 / 64, M_ / 128, 3);    // (4, 36, 3)
    gemm_mma_kernel<1><<<qkv_grid, 256, GSM_BYTES>>>(
        x, Wq, Wk, Wv, bq, bk, bv, qp, kp, vp);

    dim3 agrid(NTILE, BH_);                  // (18, 16)
    attn_mma_kernel<<<agrid, 256, SMEM_ATTN_BYTES>>>();

    dim3 o_grid(256 / 64, M_ / 128, 1);      // (4, 36, 1)
    gemm_mma_kernel<0><<<o_grid, 256, GSM_BYTES>>>(
        ctxp, Wo, Wo, Wo, bo, bo, bo, out, out, out);
}

// round 7
// speedup vs baseline: 5.3997x; 1.2438x over previous
#include <cuda_runtime.h>
#include <cstdint>

// ---------------------------------------------------------------------------
// TriangularAttention: B=2, S=48 -> N=2304, D=256, H=8, DH=32
// Round 7: attention MIO diet — fp16 PV (zero-shuffle P reuse via C-frag ==
//          A-frag identity), ldmatrix.trans for V, LDS.64 pair-permuted K,
//          exp folded to a single MUFU op. GEMMs unchanged from round 5/6.
// ---------------------------------------------------------------------------

constexpr int B_  = 2;
constexpr int S_  = 48;
constexpr int D_  = 256;
constexpr int H_  = 8;
constexpr int DH_ = 32;
constexpr int N_  = S_ * S_;     // 2304
constexpr int M_  = B_ * N_;     // 4608
constexpr int BH_ = B_ * H_;     // 16

__device__ float g_q[BH_ * N_ * DH_];    // [b*H+h][n][dh]
__device__ float g_k[BH_ * N_ * DH_];
__device__ float g_v[BH_ * N_ * DH_];
__device__ float g_ctx[M_ * D_];         // [b*N+n][d]

// ---------------- helpers ---------------------------------------------------
__device__ __forceinline__ uint32_t tf32r(float x) {
    uint32_t r;
    asm("cvt.rna.tf32.f32 %0, %1;" : "=r"(r) : "f"(x));
    return r;
}
__device__ __forceinline__ float ex2f(float x) {
    float y;
    asm("ex2.approx.ftz.f32 %0, %1;" : "=f"(y) : "f"(x));
    return y;
}
__device__ __forceinline__ uint32_t f16x2(float hi, float lo) {  // {hi,lo} pack
    uint32_t r;
    asm("cvt.rn.f16x2.f32 %0, %1, %2;" : "=r"(r) : "f"(hi), "f"(lo));
    return r;
}
__device__ __forceinline__ uint32_t smem_u32(const void* p) {
    uint32_t a;
    asm("{ .reg .u64 t; cvta.to.shared.u64 t, %1; cvt.u32.u64 %0, t; }"
        : "=r"(a) : "l"(p));
    return a;
}
__device__ __forceinline__ void mma_tf32(float* d, const uint32_t* a,
                                         uint32_t b0, uint32_t b1) {
    asm volatile(
        "mma.sync.aligned.m16n8k8.row.col.f32.tf32.tf32.f32 "
        "{%0,%1,%2,%3}, {%4,%5,%6,%7}, {%8,%9}, {%0,%1,%2,%3};"
        : "+f"(d[0]), "+f"(d[1]), "+f"(d[2]), "+f"(d[3])
        : "r"(a[0]), "r"(a[1]), "r"(a[2]), "r"(a[3]), "r"(b0), "r"(b1));
}
__device__ __forceinline__ void mma_f16(float* d, const uint32_t* a,
                                        uint32_t b0, uint32_t b1) {
    asm volatile(
        "mma.sync.aligned.m16n8k16.row.col.f32.f16.f16.f32 "
        "{%0,%1,%2,%3}, {%4,%5,%6,%7}, {%8,%9}, {%0,%1,%2,%3};"
        : "+f"(d[0]), "+f"(d[1]), "+f"(d[2]), "+f"(d[3])
        : "r"(a[0]), "r"(a[1]), "r"(a[2]), "r"(a[3]), "r"(b0), "r"(b1));
}
__device__ __forceinline__ void ldsm4t(uint32_t* r, uint32_t addr) {
    asm volatile(
        "ldmatrix.sync.aligned.m8n8.x4.trans.shared.b16 {%0,%1,%2,%3}, [%4];"
        : "=r"(r[0]), "=r"(r[1]), "=r"(r[2]), "=r"(r[3]) : "r"(addr));
}
__device__ __forceinline__ uint32_t fasu(float x) { return __float_as_uint(x); }

// ---------------------------------------------------------------------------
// Tensor-core GEMM (unchanged): out[M,256] = A @ W + bias
// ---------------------------------------------------------------------------
constexpr int GA_ST = 36;
constexpr int GW_ST = 72;
constexpr int GA_BUF = 128 * GA_ST;
constexpr int GW_BUF = 32 * GW_ST;
constexpr int GSM_BYTES = (2 * GA_BUF + 2 * GW_BUF) * 4;   // 55296

template <int HEADMAJOR>
__global__ __launch_bounds__(256) void gemm_mma_kernel(
    const float* __restrict__ A,
    const float* __restrict__ W0, const float* __restrict__ W1,
    const float* __restrict__ W2,
    const float* __restrict__ bias0, const float* __restrict__ bias1,
    const float* __restrict__ bias2,
    float* __restrict__ out0, float* __restrict__ out1,
    float* __restrict__ out2)
{
    extern __shared__ __align__(16) float sm[];

    const int z = blockIdx.z;
    const float* W    = (z == 0) ? W0 : (z == 1) ? W1 : W2;
    const float* bias = (z == 0) ? bias0 : (z == 1) ? bias1 : bias2;
    float* out        = (z == 0) ? out0 : (z == 1) ? out1 : out2;

    const int tid  = threadIdx.x;
    const int warp = tid >> 5;
    const int lane = tid & 31;
    const int gid  = lane >> 2;
    const int tig  = lane & 3;
    const int wr   = warp & 3;
    const int wc   = warp >> 2;
    const int c0   = blockIdx.x * 64;
    const int m0   = blockIdx.y * 128;

    float acc[2][4][4];
#pragma unroll
    for (int m = 0; m < 2; m++)
#pragma unroll
        for (int n = 0; n < 4; n++)
#pragma unroll
            for (int r = 0; r < 4; r++) acc[m][n][r] = 0.f;

    auto load_chunk = [&](int k0, int buf) {
        float* as = sm + buf * GA_BUF;
        float* ws = sm + 2 * GA_BUF + buf * GW_BUF;
#pragma unroll
        for (int r = 0; r < 4; r++) {
            int idx = tid + r * 256;
            int row = idx >> 3, c4 = idx & 7;
            float4 v = *(const float4*)&A[(size_t)(m0 + row) * 256 + k0 + c4 * 4];
            float4 tv;
            tv.x = __uint_as_float(tf32r(v.x));
            tv.y = __uint_as_float(tf32r(v.y));
            tv.z = __uint_as_float(tf32r(v.z));
            tv.w = __uint_as_float(tf32r(v.w));
            *(float4*)&as[row * GA_ST + c4 * 4] = tv;
        }
#pragma unroll
        for (int r = 0; r < 2; r++) {
            int idx = tid + r * 256;
            int kk = idx >> 4, c4 = idx & 15;
            float4 v = *(const float4*)&W[(size_t)(k0 + kk) * 256 + c0 + c4 * 4];
            float4 tv;
            tv.x = __uint_as_float(tf32r(v.x));
            tv.y = __uint_as_float(tf32r(v.y));
            tv.z = __uint_as_float(tf32r(v.z));
            tv.w = __uint_as_float(tf32r(v.w));
            *(float4*)&ws[kk * GW_ST + c4 * 4] = tv;
        }
    };

    load_chunk(0, 0);
    __syncthreads();

#pragma unroll 1
    for (int kc = 0; kc < 8; kc++) {
        const int buf = kc & 1;
        if (kc + 1 < 8) load_chunk((kc + 1) * 32, buf ^ 1);

        const float* as = sm + buf * GA_BUF;
        const float* ws = sm + 2 * GA_BUF + buf * GW_BUF;

#pragma unroll
        for (int ks = 0; ks < 4; ks++) {
            uint32_t a[2][4];
#pragma unroll
            for (int m = 0; m < 2; m++) {
                const float* ap = as + (size_t)(wr * 32 + m * 16 + gid) * GA_ST
                                + ks * 8 + tig;
                a[m][0] = fasu(ap[0]);
                a[m][1] = fasu(ap[8 * GA_ST]);
                a[m][2] = fasu(ap[4]);
                a[m][3] = fasu(ap[8 * GA_ST + 4]);
            }
#pragma unroll
            for (int n = 0; n < 4; n++) {
                const float* bp = ws + (size_t)(ks * 8 + tig) * GW_ST
                                + wc * 32 + n * 8 + gid;
                uint32_t b0 = fasu(bp[0]);
                uint32_t b1 = fasu(bp[4 * GW_ST]);
                mma_tf32(acc[0][n], a[0], b0, b1);
                mma_tf32(acc[1][n], a[1], b0, b1);
            }
        }
        __syncthreads();
    }

#pragma unroll
    for (int n = 0; n < 4; n++) {
        int c = c0 + wc * 32 + n * 8 + 2 * tig;
        float bv0 = bias[c], bv1 = bias[c + 1];
#pragma unroll
        for (int m = 0; m < 2; m++) {
            int row = m0 + wr * 32 + m * 16 + gid;
            float2 w0 = make_float2(acc[m][n][0] + bv0, acc[m][n][1] + bv1);
            float2 w1 = make_float2(acc[m][n][2] + bv0, acc[m][n][3] + bv1);
            if (HEADMAJOR) {
                int hh = c >> 5;
                int dh = c & 31;
                int b  = row / N_;
                int nn = row - b * N_;
                float* p = out + (((size_t)(b * H_ + hh)) * N_ + nn) * DH_ + dh;
                *(float2*)p              = w0;
                *(float2*)(p + 8 * DH_)  = w1;
            } else {
                float* p = out + (size_t)row * 256 + c;
                *(float2*)p              = w0;
                *(float2*)(p + 8 * 256)  = w1;
            }
        }
    }
}

// ---------------------------------------------------------------------------
// Flash attention: QK tf32 (pair-permuted K, LDS.64 frags), PV fp16
// (P C-frag == A-frag, V via ldmatrix.x4.trans). Key-split across warp halves,
// linear fixed-shift softmax (single ex2 per element).
// ---------------------------------------------------------------------------
constexpr int NTILE = N_ / 128;   // 18
constexpr int KST   = 40;         // K smem row stride (floats)
constexpr int VSTB  = 80;         // V smem row stride (bytes, fp16 *40)

constexpr int KB0 = 0;                    // bytes
constexpr int KB1 = 128 * KST * 4;        // 20480
constexpr int VB0 = 2 * 128 * KST * 4;    // 40960
constexpr int VB1 = VB0 + 128 * VSTB;     // 51200
constexpr int SMEM_ATTN_BYTES = VB1 + 128 * VSTB;   // 61440
constexpr int SCR_F = VB0 / 4;            // scratch (floats) overlays V0

__global__ __launch_bounds__(256, 2) void attn_mma_kernel()
{
    extern __shared__ __align__(16) float smf[];
    const int tid  = threadIdx.x;
    const int warp = tid >> 5;
    const int lane = tid & 31;
    const int gid  = lane >> 2;
    const int tig  = lane & 3;
    const int wq   = warp & 3;
    const int wk   = warp >> 2;
    const int bh   = blockIdx.y;
    const int qt   = blockIdx.x;

    const uint32_t sb = smem_u32(smf);

    const float* Qg = g_q + ((size_t)bh * N_ + qt * 128) * DH_;
    const float* Kg = g_k + (size_t)bh * N_ * DH_;
    const float* Vg = g_v + (size_t)bh * N_ * DH_;

    // exp2-folded softmax: p = 2^(q*k*CS2 - C2); constant cancels in divide.
    const float CS2 = 0.17677669529663687f * 1.4426950408889634f;
    const float C2  = 8.0f * 1.4426950408889634f;

    // ---- Q fragments (pre-scaled by CS2), held in registers ----
    uint32_t qa[2][4][4];
#pragma unroll
    for (int m = 0; m < 2; m++) {
        const float* r0 = Qg + (size_t)(wq * 32 + m * 16 + gid) * DH_;
        const float* r1 = r0 + 8 * DH_;
#pragma unroll
        for (int ks = 0; ks < 4; ks++) {
            qa[m][ks][0] = tf32r(r0[ks * 8 + tig] * CS2);
            qa[m][ks][1] = tf32r(r1[ks * 8 + tig] * CS2);
            qa[m][ks][2] = tf32r(r0[ks * 8 + tig + 4] * CS2);
            qa[m][ks][3] = tf32r(r1[ks * 8 + tig + 4] * CS2);
        }
    }

    float oacc[2][4][4];
#pragma unroll
    for (int m = 0; m < 2; m++)
#pragma unroll
        for (int n = 0; n < 4; n++)
#pragma unroll
            for (int r = 0; r < 4; r++) oacc[m][n][r] = 0.f;
    float lp[2][2] = {{0.f, 0.f}, {0.f, 0.f}};

    // ---- tile loader: K pair-permuted tf32, V fp16 natural [key][d] ----
    auto load_tile = [&](int t, int buf) {
        float* kd = smf + (buf ? KB1 / 4 : KB0 / 4);
        char*  vd = (char*)smf + (buf ? VB1 : VB0);
        const float4* ks4 = (const float4*)(Kg + (size_t)t * 128 * DH_);
        const float4* vs4 = (const float4*)(Vg + (size_t)t * 128 * DH_);
#pragma unroll
        for (int i = tid; i < 1024; i += 256) {
            int key = i >> 3, c4 = i & 7;
            float4 kv = ks4[i];
            // pair-permute: col(dh) = (dh>>3)*8 + (dh&3)*2 + ((dh>>2)&1)
            float* kr = kd + key * KST + (c4 >> 1) * 8 + (c4 & 1);
            kr[0] = __uint_as_float(tf32r(kv.x));
            kr[2] = __uint_as_float(tf32r(kv.y));
            kr[4] = __uint_as_float(tf32r(kv.z));
            kr[6] = __uint_as_float(tf32r(kv.w));
            float4 vv = vs4[i];
            uint2 hv;
            hv.x = f16x2(vv.y, vv.x);
            hv.y = f16x2(vv.w, vv.z);
            *(uint2*)(vd + key * VSTB + c4 * 8) = hv;
        }
    };

    load_tile(0, 0);
    __syncthreads();

    const int ldsm_m = lane >> 3;          // matrix index 0..3
    const int ldsm_r = lane & 7;           // row within matrix

    for (int t = 0; t < NTILE; t++) {
        const int buf = t & 1;
        if (t + 1 < NTILE) load_tile(t + 1, buf ^ 1);

        const float*  Kb   = smf + (buf ? KB1 / 4 : KB0 / 4);
        const uint32_t vbb = sb + (buf ? VB1 : VB0);

#pragma unroll
        for (int g = 0; g < 4; g++) {
            const int kb = wk * 64 + g * 16;

            // ---- S = (CS2*Q) K^T - C2 over 16 keys ----
            float s[2][2][4];
#pragma unroll
            for (int m = 0; m < 2; m++)
#pragma unroll
                for (int j = 0; j < 2; j++)
#pragma unroll
                    for (int r = 0; r < 4; r++) s[m][j][r] = -C2;

#pragma unroll
            for (int ks = 0; ks < 4; ks++) {
#pragma unroll
                for (int j = 0; j < 2; j++) {
                    unsigned long long kk = *(const unsigned long long*)
                        &Kb[(size_t)(kb + j * 8 + gid) * KST + ks * 8 + 2 * tig];
                    uint32_t b0 = (uint32_t)kk;
                    uint32_t b1 = (uint32_t)(kk >> 32);
                    mma_tf32(s[0][j], qa[0][ks], b0, b1);
                    mma_tf32(s[1][j], qa[1][ks], b0, b1);
                }
            }

            // ---- p = 2^s; pack C-frag pairs directly as fp16 A-frag ----
            uint32_t aP[2][4];
#pragma unroll
            for (int m = 0; m < 2; m++) {
                float p00 = ex2f(s[m][0][0]), p01 = ex2f(s[m][0][1]);
                float p02 = ex2f(s[m][0][2]), p03 = ex2f(s[m][0][3]);
                float p10 = ex2f(s[m][1][0]), p11 = ex2f(s[m][1][1]);
                float p12 = ex2f(s[m][1][2]), p13 = ex2f(s[m][1][3]);
                lp[m][0] += (p00 + p01) + (p10 + p11);
                lp[m][1] += (p02 + p03) + (p12 + p13);
                aP[m][0] = f16x2(p01, p00);
                aP[m][1] = f16x2(p03, p02);
                aP[m][2] = f16x2(p11, p10);
                aP[m][3] = f16x2(p13, p12);
            }

            // ---- O += P V via ldmatrix.trans + fp16 MMA ----
#pragma unroll
            for (int h = 0; h < 2; h++) {
                uint32_t vr[4];
                uint32_t addr = vbb
                    + (uint32_t)(kb + (ldsm_m & 1) * 8 + ldsm_r) * VSTB
                    + (uint32_t)((ldsm_m >> 1) * 8 + h * 16) * 2;
                ldsm4t(vr, addr);
                mma_f16(oacc[0][2 * h],     aP[0], vr[0], vr[1]);
                mma_f16(oacc[0][2 * h + 1], aP[0], vr[2], vr[3]);
                mma_f16(oacc[1][2 * h],     aP[1], vr[0], vr[1]);
                mma_f16(oacc[1][2 * h + 1], aP[1], vr[2], vr[3]);
            }
        }
        __syncthreads();
    }

    // ---- combine key-halves via scratch overlaying V0 ----
    float* sc = smf + SCR_F + wq * 1152;
    if (wk == 1) {
        int idx = 0;
#pragma unroll
        for (int m = 0; m < 2; m++)
#pragma unroll
            for (int n = 0; n < 4; n++)
#pragma unroll
                for (int r = 0; r < 4; r++)
                    sc[(idx++) * 32 + lane] = oacc[m][n][r];
#pragma unroll
        for (int m = 0; m < 2; m++)
#pragma unroll
            for (int r = 0; r < 2; r++)
                sc[1024 + (m * 2 + r) * 32 + lane] = lp[m][r];
    }
    __syncthreads();
    if (wk == 0) {
        int idx = 0;
#pragma unroll
        for (int m = 0; m < 2; m++)
#pragma unroll
            for (int n = 0; n < 4; n++)
#pragma unroll
                for (int r = 0; r < 4; r++)
                    oacc[m][n][r] += sc[(idx++) * 32 + lane];
#pragma unroll
        for (int m = 0; m < 2; m++)
#pragma unroll
            for (int r = 0; r < 2; r++)
                lp[m][r] += sc[1024 + (m * 2 + r) * 32 + lane];

#pragma unroll
        for (int m = 0; m < 2; m++)
#pragma unroll
            for (int r = 0; r < 2; r++) {
                float v = lp[m][r];
                v += __shfl_xor_sync(0xFFFFFFFFu, v, 1);
                v += __shfl_xor_sync(0xFFFFFFFFu, v, 2);
                lp[m][r] = 1.0f / v;
            }

        const int b  = bh >> 3;
        const int hh = bh & 7;
#pragma unroll
        for (int m = 0; m < 2; m++) {
            int q0 = qt * 128 + wq * 32 + m * 16 + gid;
#pragma unroll
            for (int n = 0; n < 4; n++) {
                int col = hh * 32 + n * 8 + 2 * tig;
                float2 w0, w1;
                w0.x = oacc[m][n][0] * lp[m][0];
                w0.y = oacc[m][n][1] * lp[m][0];
                w1.x = oacc[m][n][2] * lp[m][1];
                w1.y = oacc[m][n][3] * lp[m][1];
                *(float2*)&g_ctx[(size_t)(b * N_ + q0) * D_ + col]     = w0;
                *(float2*)&g_ctx[(size_t)(b * N_ + q0 + 8) * D_ + col] = w1;
            }
        }
    }
}

// ---------------------------------------------------------------------------
extern "C" void kernel_launch(void* const* d_in, const int* in_sizes, int n_in,
                              void* d_out, int out_size)
{
    const float* x  = (const float*)d_in[0];
    const float* Wq = (const float*)d_in[1];
    const float* bq = (const float*)d_in[2];
    const float* Wk = (const float*)d_in[3];
    const float* bk = (const float*)d_in[4];
    const float* Wv = (const float*)d_in[5];
    const float* bv = (const float*)d_in[6];
    const float* Wo = (const float*)d_in[7];
    const float* bo = (const float*)d_in[8];
    float* out = (float*)d_out;

    float *qp, *kp, *vp, *ctxp;
    cudaGetSymbolAddress((void**)&qp,   g_q);
    cudaGetSymbolAddress((void**)&kp,   g_k);
    cudaGetSymbolAddress((void**)&vp,   g_v);
    cudaGetSymbolAddress((void**)&ctxp, g_ctx);

    cudaFuncSetAttribute(gemm_mma_kernel<1>,
                         cudaFuncAttributeMaxDynamicSharedMemorySize, GSM_BYTES);
    cudaFuncSetAttribute(gemm_mma_kernel<0>,
                         cudaFuncAttributeMaxDynamicSharedMemorySize, GSM_BYTES);
    cudaFuncSetAttribute(attn_mma_kernel,
                         cudaFuncAttributeMaxDynamicSharedMemorySize,
                         SMEM_ATTN_BYTES);

    dim3 qkv_grid(256 / 64, M_ / 128, 3);    // (4, 36, 3)
    gemm_mma_kernel<1><<<qkv_grid, 256, GSM_BYTES>>>(
        x, Wq, Wk, Wv, bq, bk, bv, qp, kp, vp);

    dim3 agrid(NTILE, BH_);                  // (18, 16)
    attn_mma_kernel<<<agrid, 256, SMEM_ATTN_BYTES>>>();

    dim3 o_grid(256 / 64, M_ / 128, 1);      // (4, 36, 1)
    gemm_mma_kernel<0><<<o_grid, 256, GSM_BYTES>>>(
        ctxp, Wo, Wo, Wo, bo, bo, bo, out, out, out);
}

// round 8
// speedup vs baseline: 7.8296x; 1.4500x over previous
#include <cuda_runtime.h>
#include <cstdint>

// ---------------------------------------------------------------------------
// TriangularAttention: B=2, S=48 -> N=2304, D=256, H=8, DH=32
// Round 8: all-fp16 operands (fp32 accumulate): fp16 QK via non-trans
//          ldmatrix B-frags, ex2.approx.f16x2 softmax (MUFU halved),
//          fp16 GEMMs with ldmatrix A/W fragments.
// ---------------------------------------------------------------------------

constexpr int B_  = 2;
constexpr int S_  = 48;
constexpr int D_  = 256;
constexpr int H_  = 8;
constexpr int DH_ = 32;
constexpr int N_  = S_ * S_;     // 2304
constexpr int M_  = B_ * N_;     // 4608
constexpr int BH_ = B_ * H_;     // 16

__device__ float g_q[BH_ * N_ * DH_];    // [b*H+h][n][dh]
__device__ float g_k[BH_ * N_ * DH_];
__device__ float g_v[BH_ * N_ * DH_];
__device__ float g_ctx[M_ * D_];         // [b*N+n][d]

// ---------------- helpers ---------------------------------------------------
__device__ __forceinline__ float ex2f(float x) {
    float y;
    asm("ex2.approx.ftz.f32 %0, %1;" : "=f"(y) : "f"(x));
    return y;
}
__device__ __forceinline__ uint32_t f16x2(float hi, float lo) {  // {hi,lo}
    uint32_t r;
    asm("cvt.rn.f16x2.f32 %0, %1, %2;" : "=r"(r) : "f"(hi), "f"(lo));
    return r;
}
__device__ __forceinline__ uint32_t hadd2(uint32_t a, uint32_t b) {
    uint32_t d;
    asm("add.rn.f16x2 %0, %1, %2;" : "=r"(d) : "r"(a), "r"(b));
    return d;
}
__device__ __forceinline__ uint32_t h2ex2(uint32_t a) {
    uint32_t d;
    asm("ex2.approx.f16x2 %0, %1;" : "=r"(d) : "r"(a));
    return d;
}
__device__ __forceinline__ float2 h2f2(uint32_t h) {
    float lo, hi;
    asm("{ .reg .b16 l, m; mov.b32 {l, m}, %2;\n\t"
        "cvt.f32.f16 %0, l; cvt.f32.f16 %1, m; }"
        : "=f"(lo), "=f"(hi) : "r"(h));
    return make_float2(lo, hi);
}
__device__ __forceinline__ uint32_t smem_u32(const void* p) {
    uint32_t a;
    asm("{ .reg .u64 t; cvta.to.shared.u64 t, %1; cvt.u32.u64 %0, t; }"
        : "=r"(a) : "l"(p));
    return a;
}
__device__ __forceinline__ void mma_f16(float* d, const uint32_t* a,
                                        uint32_t b0, uint32_t b1) {
    asm volatile(
        "mma.sync.aligned.m16n8k16.row.col.f32.f16.f16.f32 "
        "{%0,%1,%2,%3}, {%4,%5,%6,%7}, {%8,%9}, {%0,%1,%2,%3};"
        : "+f"(d[0]), "+f"(d[1]), "+f"(d[2]), "+f"(d[3])
        : "r"(a[0]), "r"(a[1]), "r"(a[2]), "r"(a[3]), "r"(b0), "r"(b1));
}
__device__ __forceinline__ void ldsm4(uint32_t* r, uint32_t addr) {   // non-trans
    asm volatile(
        "ldmatrix.sync.aligned.m8n8.x4.shared.b16 {%0,%1,%2,%3}, [%4];"
        : "=r"(r[0]), "=r"(r[1]), "=r"(r[2]), "=r"(r[3]) : "r"(addr));
}
__device__ __forceinline__ void ldsm4t(uint32_t* r, uint32_t addr) {  // trans
    asm volatile(
        "ldmatrix.sync.aligned.m8n8.x4.trans.shared.b16 {%0,%1,%2,%3}, [%4];"
        : "=r"(r[0]), "=r"(r[1]), "=r"(r[2]), "=r"(r[3]) : "r"(addr));
}

// ---------------------------------------------------------------------------
// fp16 tensor-core GEMM: out[M,256] = A[M,256] @ W[256,256] + bias.
// CTA 128x64, 256 thr (8 warps 4x2), k-chunks 32, double-buffered fp16 SMEM.
// A [row][k] stride 80B (ldsm non-trans -> A-frag); W [k][c] stride 144B
// (ldsm trans -> B-frag, same pattern as V in attention).
// ---------------------------------------------------------------------------
constexpr int GA_BYTES = 128 * 80;    // 10240
constexpr int GW_BYTES = 32 * 144;    // 4608
constexpr int GSM_BYTES = 2 * GA_BYTES + 2 * GW_BYTES;   // 29696

template <int HEADMAJOR>
__global__ __launch_bounds__(256) void gemm_mma_kernel(
    const float* __restrict__ A,
    const float* __restrict__ W0, const float* __restrict__ W1,
    const float* __restrict__ W2,
    const float* __restrict__ bias0, const float* __restrict__ bias1,
    const float* __restrict__ bias2,
    float* __restrict__ out0, float* __restrict__ out1,
    float* __restrict__ out2)
{
    extern __shared__ __align__(16) char smc[];

    const int z = blockIdx.z;
    const float* W    = (z == 0) ? W0 : (z == 1) ? W1 : W2;
    const float* bias = (z == 0) ? bias0 : (z == 1) ? bias1 : bias2;
    float* out        = (z == 0) ? out0 : (z == 1) ? out1 : out2;

    const int tid  = threadIdx.x;
    const int warp = tid >> 5;
    const int lane = tid & 31;
    const int gid  = lane >> 2;
    const int tig  = lane & 3;
    const int wr   = warp & 3;
    const int wc   = warp >> 2;
    const int c0   = blockIdx.x * 64;
    const int m0   = blockIdx.y * 128;
    const int mm   = lane >> 3;         // ldmatrix matrix id
    const int mr   = lane & 7;          // row within matrix

    const uint32_t sb = smem_u32(smc);

    float acc[2][4][4];
#pragma unroll
    for (int m = 0; m < 2; m++)
#pragma unroll
        for (int n = 0; n < 4; n++)
#pragma unroll
            for (int r = 0; r < 4; r++) acc[m][n][r] = 0.f;

    auto load_chunk = [&](int k0, int buf) {
        char* as = smc + buf * GA_BYTES;
        char* ws = smc + 2 * GA_BYTES + buf * GW_BYTES;
        // A: 128 rows x 32 k -> fp16, stride 80B
#pragma unroll
        for (int r = 0; r < 4; r++) {
            int idx = tid + r * 256;
            int row = idx >> 3, c4 = idx & 7;
            float4 v = *(const float4*)&A[(size_t)(m0 + row) * 256 + k0 + c4 * 4];
            uint2 hv;
            hv.x = f16x2(v.y, v.x);
            hv.y = f16x2(v.w, v.z);
            *(uint2*)(as + row * 80 + c4 * 8) = hv;
        }
        // W: 32 k x 64 c -> fp16, stride 144B
#pragma unroll
        for (int r = 0; r < 2; r++) {
            int idx = tid + r * 256;
            int kk = idx >> 4, c4 = idx & 15;
            float4 v = *(const float4*)&W[(size_t)(k0 + kk) * 256 + c0 + c4 * 4];
            uint2 hv;
            hv.x = f16x2(v.y, v.x);
            hv.y = f16x2(v.w, v.z);
            *(uint2*)(ws + kk * 144 + c4 * 8) = hv;
        }
    };

    load_chunk(0, 0);
    __syncthreads();

#pragma unroll 1
    for (int kc = 0; kc < 8; kc++) {
        const int buf = kc & 1;
        if (kc + 1 < 8) load_chunk((kc + 1) * 32, buf ^ 1);

        const uint32_t as = sb + buf * GA_BYTES;
        const uint32_t ws = sb + 2 * GA_BYTES + buf * GW_BYTES;

#pragma unroll
        for (int h = 0; h < 2; h++) {          // k16 within chunk
            uint32_t a[2][4];
#pragma unroll
            for (int mt = 0; mt < 2; mt++) {
                // x4 non-trans: {rows0-7 kLo, rows8-15 kLo, rows0-7 kHi, rows8-15 kHi}
                uint32_t addr = as
                    + (uint32_t)(wr * 32 + mt * 16 + (mm & 1) * 8 + mr) * 80
                    + (uint32_t)(h * 32 + (mm >> 1) * 16);
                ldsm4(a[mt], addr);
            }
#pragma unroll
            for (int nb = 0; nb < 2; nb++) {
                // x4 trans: {k0-7 cLo, k8-15 cLo, k0-7 cHi, k8-15 cHi}
                uint32_t w[4];
                uint32_t addr = ws
                    + (uint32_t)(h * 16 + (mm & 1) * 8 + mr) * 144
                    + (uint32_t)(wc * 32 + nb * 16 + (mm >> 1) * 8) * 2;
                ldsm4t(w, addr);
                mma_f16(acc[0][2 * nb],     a[0], w[0], w[1]);
                mma_f16(acc[0][2 * nb + 1], a[0], w[2], w[3]);
                mma_f16(acc[1][2 * nb],     a[1], w[0], w[1]);
                mma_f16(acc[1][2 * nb + 1], a[1], w[2], w[3]);
            }
        }
        __syncthreads();
    }

#pragma unroll
    for (int n = 0; n < 4; n++) {
        int c = c0 + wc * 32 + n * 8 + 2 * tig;
        float bv0 = bias[c], bv1 = bias[c + 1];
#pragma unroll
        for (int m = 0; m < 2; m++) {
            int row = m0 + wr * 32 + m * 16 + gid;
            float2 w0 = make_float2(acc[m][n][0] + bv0, acc[m][n][1] + bv1);
            float2 w1 = make_float2(acc[m][n][2] + bv0, acc[m][n][3] + bv1);
            if (HEADMAJOR) {
                int hh = c >> 5;
                int dh = c & 31;
                int b  = row / N_;
                int nn = row - b * N_;
                float* p = out + (((size_t)(b * H_ + hh)) * N_ + nn) * DH_ + dh;
                *(float2*)p              = w0;
                *(float2*)(p + 8 * DH_)  = w1;
            } else {
                float* p = out + (size_t)row * 256 + c;
                *(float2*)p              = w0;
                *(float2*)(p + 8 * 256)  = w1;
            }
        }
    }
}

// ---------------------------------------------------------------------------
// fp16 flash attention. K,V stored fp16 [key][dh], 80B rows.
// QK: non-trans ldmatrix B-frags + fp16 MMA. Softmax: pack-then-ex2.f16x2.
// PV: C-frag==A-frag identity + trans ldmatrix V.
// Key-split across warp halves, linear fixed-shift softmax.
// ---------------------------------------------------------------------------
constexpr int NTILE = N_ / 128;   // 18
constexpr int KB0 = 0;            // byte offsets
constexpr int KB1 = 128 * 80;     // 10240
constexpr int VB0 = 2 * 128 * 80; // 20480
constexpr int VB1 = VB0 + 128 * 80;
constexpr int SMEM_ATTN_BYTES = VB1 + 128 * 80;  // 40960

__global__ __launch_bounds__(256, 2) void attn_mma_kernel()
{
    extern __shared__ __align__(16) float smf[];
    char* smc = (char*)smf;
    const int tid  = threadIdx.x;
    const int warp = tid >> 5;
    const int lane = tid & 31;
    const int gid  = lane >> 2;
    const int tig  = lane & 3;
    const int wq   = warp & 3;
    const int wk   = warp >> 2;
    const int bh   = blockIdx.y;
    const int qt   = blockIdx.x;
    const int mm   = lane >> 3;
    const int mr   = lane & 7;

    const uint32_t sb = smem_u32(smf);

    const float* Qg = g_q + ((size_t)bh * N_ + qt * 128) * DH_;
    const float* Kg = g_k + (size_t)bh * N_ * DH_;
    const float* Vg = g_v + (size_t)bh * N_ * DH_;

    // p = 2^(q·k·CS2 - C2); constant cancels in the final divide.
    const float CS2 = 0.17677669529663687f * 1.4426950408889634f;
    const float C2  = 8.0f * 1.4426950408889634f;

    // ---- Q fp16 A-frags (pre-scaled by CS2): qa[m][k16][4] ----
    uint32_t qa[2][2][4];
#pragma unroll
    for (int m = 0; m < 2; m++) {
        const float* r0 = Qg + (size_t)(wq * 32 + m * 16 + gid) * DH_;
        const float* r1 = r0 + 8 * DH_;
#pragma unroll
        for (int h = 0; h < 2; h++) {
            int k0 = h * 16 + 2 * tig;
            qa[m][h][0] = f16x2(r0[k0 + 1] * CS2, r0[k0] * CS2);
            qa[m][h][1] = f16x2(r1[k0 + 1] * CS2, r1[k0] * CS2);
            qa[m][h][2] = f16x2(r0[k0 + 9] * CS2, r0[k0 + 8] * CS2);
            qa[m][h][3] = f16x2(r1[k0 + 9] * CS2, r1[k0 + 8] * CS2);
        }
    }

    float oacc[2][4][4];
#pragma unroll
    for (int m = 0; m < 2; m++)
#pragma unroll
        for (int n = 0; n < 4; n++)
#pragma unroll
            for (int r = 0; r < 4; r++) oacc[m][n][r] = 0.f;
    float lp[2][2] = {{0.f, 0.f}, {0.f, 0.f}};

    // ---- tile loader: K and V fp16 [key][dh], 80B stride ----
    auto load_tile = [&](int t, int buf) {
        char* kd = smc + (buf ? KB1 : KB0);
        char* vd = smc + (buf ? VB1 : VB0);
        const float4* ks4 = (const float4*)(Kg + (size_t)t * 128 * DH_);
        const float4* vs4 = (const float4*)(Vg + (size_t)t * 128 * DH_);
#pragma unroll
        for (int i = tid; i < 1024; i += 256) {
            int key = i >> 3, c4 = i & 7;
            float4 kv = ks4[i];
            uint2 hk;
            hk.x = f16x2(kv.y, kv.x);
            hk.y = f16x2(kv.w, kv.z);
            *(uint2*)(kd + key * 80 + c4 * 8) = hk;
            float4 vv = vs4[i];
            uint2 hv;
            hv.x = f16x2(vv.y, vv.x);
            hv.y = f16x2(vv.w, vv.z);
            *(uint2*)(vd + key * 80 + c4 * 8) = hv;
        }
    };

    load_tile(0, 0);
    __syncthreads();

    for (int t = 0; t < NTILE; t++) {
        const int buf = t & 1;
        if (t + 1 < NTILE) load_tile(t + 1, buf ^ 1);

        const uint32_t kbb = sb + (buf ? KB1 : KB0);
        const uint32_t vbb = sb + (buf ? VB1 : VB0);

#pragma unroll
        for (int g = 0; g < 4; g++) {
            const int kb = wk * 64 + g * 16;

            // ---- S = (CS2·Q)K^T − C2 over 16 keys, fp16 MMA ----
            float s[2][2][4];
#pragma unroll
            for (int m = 0; m < 2; m++)
#pragma unroll
                for (int j = 0; j < 2; j++)
#pragma unroll
                    for (int r = 0; r < 4; r++) s[m][j][r] = -C2;

#pragma unroll
            for (int h = 0; h < 2; h++) {
                // non-trans x4 on K rows: {keys0-7 dhLo, keys0-7 dhHi,
                //                          keys8-15 dhLo, keys8-15 dhHi}
                uint32_t kr[4];
                uint32_t addr = kbb
                    + (uint32_t)(kb + (mm >> 1) * 8 + mr) * 80
                    + (uint32_t)((mm & 1) * 16 + h * 32);
                ldsm4(kr, addr);
                mma_f16(s[0][0], qa[0][h], kr[0], kr[1]);
                mma_f16(s[0][1], qa[0][h], kr[2], kr[3]);
                mma_f16(s[1][0], qa[1][h], kr[0], kr[1]);
                mma_f16(s[1][1], qa[1][h], kr[2], kr[3]);
            }

            // ---- pack pairs -> ex2.f16x2 -> P A-frags + lsum ----
            uint32_t aP[2][4];
#pragma unroll
            for (int m = 0; m < 2; m++) {
                aP[m][0] = h2ex2(f16x2(s[m][0][1], s[m][0][0]));
                aP[m][1] = h2ex2(f16x2(s[m][0][3], s[m][0][2]));
                aP[m][2] = h2ex2(f16x2(s[m][1][1], s[m][1][0]));
                aP[m][3] = h2ex2(f16x2(s[m][1][3], s[m][1][2]));
                float2 f0 = h2f2(hadd2(aP[m][0], aP[m][2]));  // row gid
                float2 f1 = h2f2(hadd2(aP[m][1], aP[m][3]));  // row gid+8
                lp[m][0] += f0.x + f0.y;
                lp[m][1] += f1.x + f1.y;
            }

            // ---- O += P V via trans ldmatrix + fp16 MMA ----
#pragma unroll
            for (int h = 0; h < 2; h++) {
                uint32_t vr[4];
                uint32_t addr = vbb
                    + (uint32_t)(kb + (mm & 1) * 8 + mr) * 80
                    + (uint32_t)((mm >> 1) * 8 + h * 16) * 2;
                ldsm4t(vr, addr);
                mma_f16(oacc[0][2 * h],     aP[0], vr[0], vr[1]);
                mma_f16(oacc[0][2 * h + 1], aP[0], vr[2], vr[3]);
                mma_f16(oacc[1][2 * h],     aP[1], vr[0], vr[1]);
                mma_f16(oacc[1][2 * h + 1], aP[1], vr[2], vr[3]);
            }
        }
        __syncthreads();
    }

    // ---- combine key-halves via scratch (all SMEM dead now) ----
    float* sc = smf + wq * 1152;
    if (wk == 1) {
        int idx = 0;
#pragma unroll
        for (int m = 0; m < 2; m++)
#pragma unroll
            for (int n = 0; n < 4; n++)
#pragma unroll
                for (int r = 0; r < 4; r++)
                    sc[(idx++) * 32 + lane] = oacc[m][n][r];
#pragma unroll
        for (int m = 0; m < 2; m++)
#pragma unroll
            for (int r = 0; r < 2; r++)
                sc[1024 + (m * 2 + r) * 32 + lane] = lp[m][r];
    }
    __syncthreads();
    if (wk == 0) {
        int idx = 0;
#pragma unroll
        for (int m = 0; m < 2; m++)
#pragma unroll
            for (int n = 0; n < 4; n++)
#pragma unroll
                for (int r = 0; r < 4; r++)
                    oacc[m][n][r] += sc[(idx++) * 32 + lane];
#pragma unroll
        for (int m = 0; m < 2; m++)
#pragma unroll
            for (int r = 0; r < 2; r++)
                lp[m][r] += sc[1024 + (m * 2 + r) * 32 + lane];

#pragma unroll
        for (int m = 0; m < 2; m++)
#pragma unroll
            for (int r = 0; r < 2; r++) {
                float v = lp[m][r];
                v += __shfl_xor_sync(0xFFFFFFFFu, v, 1);
                v += __shfl_xor_sync(0xFFFFFFFFu, v, 2);
                lp[m][r] = 1.0f / v;
            }

        const int b  = bh >> 3;
        const int hh = bh & 7;
#pragma unroll
        for (int m = 0; m < 2; m++) {
            int q0 = qt * 128 + wq * 32 + m * 16 + gid;
#pragma unroll
            for (int n = 0; n < 4; n++) {
                int col = hh * 32 + n * 8 + 2 * tig;
                float2 w0, w1;
                w0.x = oacc[m][n][0] * lp[m][0];
                w0.y = oacc[m][n][1] * lp[m][0];
                w1.x = oacc[m][n][2] * lp[m][1];
                w1.y = oacc[m][n][3] * lp[m][1];
                *(float2*)&g_ctx[(size_t)(b * N_ + q0) * D_ + col]     = w0;
                *(float2*)&g_ctx[(size_t)(b * N_ + q0 + 8) * D_ + col] = w1;
            }
        }
    }
}

// ---------------------------------------------------------------------------
extern "C" void kernel_launch(void* const* d_in, const int* in_sizes, int n_in,
                              void* d_out, int out_size)
{
    const float* x  = (const float*)d_in[0];
    const float* Wq = (const float*)d_in[1];
    const float* bq = (const float*)d_in[2];
    const float* Wk = (const float*)d_in[3];
    const float* bk = (const float*)d_in[4];
    const float* Wv = (const float*)d_in[5];
    const float* bv = (const float*)d_in[6];
    const float* Wo = (const float*)d_in[7];
    const float* bo = (const float*)d_in[8];
    float* out = (float*)d_out;

    float *qp, *kp, *vp, *ctxp;
    cudaGetSymbolAddress((void**)&qp,   g_q);
    cudaGetSymbolAddress((void**)&kp,   g_k);
    cudaGetSymbolAddress((void**)&vp,   g_v);
    cudaGetSymbolAddress((void**)&ctxp, g_ctx);

    cudaFuncSetAttribute(gemm_mma_kernel<1>,
                         cudaFuncAttributeMaxDynamicSharedMemorySize, GSM_BYTES);
    cudaFuncSetAttribute(gemm_mma_kernel<0>,
                         cudaFuncAttributeMaxDynamicSharedMemorySize, GSM_BYTES);
    cudaFuncSetAttribute(attn_mma_kernel,
                         cudaFuncAttributeMaxDynamicSharedMemorySize,
                         SMEM_ATTN_BYTES);

    dim3 qkv_grid(256 / 64, M_ / 128, 3);    // (4, 36, 3)
    gemm_mma_kernel<1><<<qkv_grid, 256, GSM_BYTES>>>(
        x, Wq, Wk, Wv, bq, bk, bv, qp, kp, vp);

    dim3 agrid(NTILE, BH_);                  // (18, 16)
    attn_mma_kernel<<<agrid, 256, SMEM_ATTN_BYTES>>>();

    dim3 o_grid(256 / 64, M_ / 128, 1);      // (4, 36, 1)
    gemm_mma_kernel<0><<<o_grid, 256, GSM_BYTES>>>(
        ctxp, Wo, Wo, Wo, bo, bo, bo, out, out, out);
}

// round 9
// speedup vs baseline: 8.8689x; 1.1327x over previous
#include <cuda_runtime.h>
#include <cuda_fp16.h>
#include <cstdint>

// ---------------------------------------------------------------------------
// TriangularAttention: B=2, S=48 -> N=2304, D=256, H=8, DH=32
// Round 9: fp16 end-to-end dataflow. One-shot cvt kernel (x, W -> fp16);
//          all GEMM/attention SMEM loaders are pure cp.async 16B copies;
//          q/k/v/ctx stored fp16 (q pre-scaled). Math identical to round 8.
// ---------------------------------------------------------------------------

constexpr int B_  = 2;
constexpr int S_  = 48;
constexpr int D_  = 256;
constexpr int H_  = 8;
constexpr int DH_ = 32;
constexpr int N_  = S_ * S_;     // 2304
constexpr int M_  = B_ * N_;     // 4608
constexpr int BH_ = B_ * H_;     // 16

// fp16 storage (uint4 for 16B alignment)
__device__ uint4 g_qh_[BH_ * N_ * DH_ / 8];
__device__ uint4 g_kh_[BH_ * N_ * DH_ / 8];
__device__ uint4 g_vh_[BH_ * N_ * DH_ / 8];
__device__ uint4 g_xh_[M_ * D_ / 8];
__device__ uint4 g_wh_[4 * D_ * D_ / 8];
__device__ uint4 g_ctxh_[M_ * D_ / 8];

// softmax: p = 2^(q·k·CS2 − C2); C2 cancels in the divide.
constexpr float CS2F = 0.17677669529663687f * 1.4426950408889634f;
constexpr float C2F  = 8.0f * 1.4426950408889634f;

// ---------------- helpers ---------------------------------------------------
__device__ __forceinline__ uint32_t f16x2(float hi, float lo) {  // {hi,lo}
    uint32_t r;
    asm("cvt.rn.f16x2.f32 %0, %1, %2;" : "=r"(r) : "f"(hi), "f"(lo));
    return r;
}
__device__ __forceinline__ uint32_t hadd2(uint32_t a, uint32_t b) {
    uint32_t d;
    asm("add.rn.f16x2 %0, %1, %2;" : "=r"(d) : "r"(a), "r"(b));
    return d;
}
__device__ __forceinline__ uint32_t h2ex2(uint32_t a) {
    uint32_t d;
    asm("ex2.approx.f16x2 %0, %1;" : "=r"(d) : "r"(a));
    return d;
}
__device__ __forceinline__ float2 h2f2(uint32_t h) {
    float lo, hi;
    asm("{ .reg .b16 l, m; mov.b32 {l, m}, %2;\n\t"
        "cvt.f32.f16 %0, l; cvt.f32.f16 %1, m; }"
        : "=f"(lo), "=f"(hi) : "r"(h));
    return make_float2(lo, hi);
}
__device__ __forceinline__ uint32_t smem_u32(const void* p) {
    uint32_t a;
    asm("{ .reg .u64 t; cvta.to.shared.u64 t, %1; cvt.u32.u64 %0, t; }"
        : "=r"(a) : "l"(p));
    return a;
}
__device__ __forceinline__ void mma_f16(float* d, const uint32_t* a,
                                        uint32_t b0, uint32_t b1) {
    asm volatile(
        "mma.sync.aligned.m16n8k16.row.col.f32.f16.f16.f32 "
        "{%0,%1,%2,%3}, {%4,%5,%6,%7}, {%8,%9}, {%0,%1,%2,%3};"
        : "+f"(d[0]), "+f"(d[1]), "+f"(d[2]), "+f"(d[3])
        : "r"(a[0]), "r"(a[1]), "r"(a[2]), "r"(a[3]), "r"(b0), "r"(b1));
}
__device__ __forceinline__ void ldsm4(uint32_t* r, uint32_t addr) {   // non-trans
    asm volatile(
        "ldmatrix.sync.aligned.m8n8.x4.shared.b16 {%0,%1,%2,%3}, [%4];"
        : "=r"(r[0]), "=r"(r[1]), "=r"(r[2]), "=r"(r[3]) : "r"(addr));
}
__device__ __forceinline__ void ldsm4t(uint32_t* r, uint32_t addr) {  // trans
    asm volatile(
        "ldmatrix.sync.aligned.m8n8.x4.trans.shared.b16 {%0,%1,%2,%3}, [%4];"
        : "=r"(r[0]), "=r"(r[1]), "=r"(r[2]), "=r"(r[3]) : "r"(addr));
}
__device__ __forceinline__ void cpa16(uint32_t dst, const void* src) {
    asm volatile("cp.async.cg.shared.global [%0], [%1], 16;"
                 :: "r"(dst), "l"(src));
}
__device__ __forceinline__ void cp_commit() {
    asm volatile("cp.async.commit_group;");
}
template <int NWAIT>
__device__ __forceinline__ void cp_wait() {
    asm volatile("cp.async.wait_group %0;" :: "n"(NWAIT));
}

// ---------------------------------------------------------------------------
// One-shot fp32 -> fp16 conversion: x and all four weight matrices.
// ---------------------------------------------------------------------------
__global__ __launch_bounds__(256) void cvt_kernel(
    const float* __restrict__ x,
    const float* __restrict__ Wq, const float* __restrict__ Wk,
    const float* __restrict__ Wv, const float* __restrict__ Wo,
    __half* __restrict__ xh, __half* __restrict__ wh)
{
    const int tid    = blockIdx.x * 256 + threadIdx.x;
    const int stride = gridDim.x * 256;
    auto seg = [&](const float* s, __half* d, int n4) {
        for (int i = tid; i < n4; i += stride) {
            float4 v = ((const float4*)s)[i];
            uint2 h;
            h.x = f16x2(v.y, v.x);
            h.y = f16x2(v.w, v.z);
            ((uint2*)d)[i] = h;
        }
    };
    seg(x,  xh,                M_ * D_ / 4);
    seg(Wq, wh,                D_ * D_ / 4);
    seg(Wk, wh + D_ * D_,      D_ * D_ / 4);
    seg(Wv, wh + 2 * D_ * D_,  D_ * D_ / 4);
    seg(Wo, wh + 3 * D_ * D_,  D_ * D_ / 4);
}

// ---------------------------------------------------------------------------
// fp16 GEMM: out[M,256] = A[M,256] @ W[256,256] + bias
// CTA 128x64, 8 warps (4x2), k-chunks of 32, cp.async double buffering.
// A [row][k] 80B stride (ldsm -> A-frag); W [k][c] 144B stride (ldsm.trans).
// QKV=1: three fp16 head-major outputs (z selects), q scaled by CS2.
// QKV=0: single f32 row-major output.
// ---------------------------------------------------------------------------
constexpr int GA_BYTES = 128 * 80;    // 10240
constexpr int GW_BYTES = 32 * 144;    // 4608
constexpr int GSM_BYTES = 2 * GA_BYTES + 2 * GW_BYTES;   // 29696

template <int QKV>
__global__ __launch_bounds__(256) void gemm_mma_kernel(
    const __half* __restrict__ Ah, const __half* __restrict__ Whb,
    const float* __restrict__ bias0, const float* __restrict__ bias1,
    const float* __restrict__ bias2,
    __half* __restrict__ o0h, __half* __restrict__ o1h,
    __half* __restrict__ o2h, float* __restrict__ outf)
{
    extern __shared__ __align__(16) char smc[];

    const int z = blockIdx.z;
    const __half* W   = Whb + (size_t)z * D_ * D_;
    const float* bias = (z == 0) ? bias0 : (z == 1) ? bias1 : bias2;
    __half* oh        = (z == 0) ? o0h : (z == 1) ? o1h : o2h;
    const float sc    = (QKV && z == 0) ? CS2F : 1.0f;

    const int tid  = threadIdx.x;
    const int warp = tid >> 5;
    const int lane = tid & 31;
    const int gid  = lane >> 2;
    const int tig  = lane & 3;
    const int wr   = warp & 3;
    const int wc   = warp >> 2;
    const int c0   = blockIdx.x * 64;
    const int m0   = blockIdx.y * 128;
    const int mm   = lane >> 3;
    const int mr   = lane & 7;

    const uint32_t sb = smem_u32(smc);

    float acc[2][4][4];
#pragma unroll
    for (int m = 0; m < 2; m++)
#pragma unroll
        for (int n = 0; n < 4; n++)
#pragma unroll
            for (int r = 0; r < 4; r++) acc[m][n][r] = 0.f;

    auto load_chunk = [&](int k0, int buf) {
        uint32_t as = sb + buf * GA_BYTES;
        uint32_t ws = sb + 2 * GA_BYTES + buf * GW_BYTES;
        const char* Ab = (const char*)Ah + ((size_t)m0 * 256 + k0) * 2;
        const char* Wb = (const char*)W + ((size_t)k0 * 256 + c0) * 2;
#pragma unroll
        for (int r = 0; r < 2; r++) {
            int idx = tid + r * 256;           // 0..511
            int row = idx >> 2, c = idx & 3;
            cpa16(as + row * 80 + c * 16, Ab + (size_t)row * 512 + c * 16);
        }
        {
            int kk = tid >> 3, c8 = tid & 7;   // 32 x 8 chunks
            cpa16(ws + kk * 144 + c8 * 16, Wb + (size_t)kk * 512 + c8 * 16);
        }
    };

    load_chunk(0, 0);
    cp_commit();

#pragma unroll 1
    for (int kc = 0; kc < 8; kc++) {
        const int buf = kc & 1;
        cp_wait<0>();
        __syncthreads();
        if (kc + 1 < 8) {
            load_chunk((kc + 1) * 32, buf ^ 1);
            cp_commit();
        }

        const uint32_t as = sb + buf * GA_BYTES;
        const uint32_t ws = sb + 2 * GA_BYTES + buf * GW_BYTES;

#pragma unroll
        for (int h = 0; h < 2; h++) {
            uint32_t a[2][4];
#pragma unroll
            for (int mt = 0; mt < 2; mt++) {
                uint32_t addr = as
                    + (uint32_t)(wr * 32 + mt * 16 + (mm & 1) * 8 + mr) * 80
                    + (uint32_t)(h * 32 + (mm >> 1) * 16);
                ldsm4(a[mt], addr);
            }
#pragma unroll
            for (int nb = 0; nb < 2; nb++) {
                uint32_t w[4];
                uint32_t addr = ws
                    + (uint32_t)(h * 16 + (mm & 1) * 8 + mr) * 144
                    + (uint32_t)(wc * 32 + nb * 16 + (mm >> 1) * 8) * 2;
                ldsm4t(w, addr);
                mma_f16(acc[0][2 * nb],     a[0], w[0], w[1]);
                mma_f16(acc[0][2 * nb + 1], a[0], w[2], w[3]);
                mma_f16(acc[1][2 * nb],     a[1], w[0], w[1]);
                mma_f16(acc[1][2 * nb + 1], a[1], w[2], w[3]);
            }
        }
        __syncthreads();
    }

#pragma unroll
    for (int n = 0; n < 4; n++) {
        int c = c0 + wc * 32 + n * 8 + 2 * tig;
        float bv0 = bias[c], bv1 = bias[c + 1];
#pragma unroll
        for (int m = 0; m < 2; m++) {
            int row = m0 + wr * 32 + m * 16 + gid;
            if (QKV) {
                int hh = c >> 5;
                int dh = c & 31;
                int b  = row / N_;
                int nn = row - b * N_;
                __half* p = oh + (((size_t)(b * H_ + hh)) * N_ + nn) * DH_ + dh;
                *(uint32_t*)p = f16x2((acc[m][n][1] + bv1) * sc,
                                      (acc[m][n][0] + bv0) * sc);
                *(uint32_t*)(p + 8 * DH_) = f16x2((acc[m][n][3] + bv1) * sc,
                                                  (acc[m][n][2] + bv0) * sc);
            } else {
                float* p = outf + (size_t)row * 256 + c;
                *(float2*)p = make_float2(acc[m][n][0] + bv0, acc[m][n][1] + bv1);
                *(float2*)(p + 8 * 256) =
                    make_float2(acc[m][n][2] + bv0, acc[m][n][3] + bv1);
            }
        }
    }
}

// ---------------------------------------------------------------------------
// fp16 flash attention (math identical to round 8), cp.async loaders,
// fp16 q (pre-scaled) / k / v inputs, fp16 ctx output.
// ---------------------------------------------------------------------------
constexpr int NTILE = N_ / 128;   // 18
constexpr int KB0 = 0;
constexpr int KB1 = 128 * 80;     // 10240
constexpr int VB0 = 2 * 128 * 80;
constexpr int VB1 = VB0 + 128 * 80;
constexpr int SMEM_ATTN_BYTES = VB1 + 128 * 80;  // 40960

__global__ __launch_bounds__(256, 2) void attn_mma_kernel(
    const __half* __restrict__ Qh, const __half* __restrict__ Kh,
    const __half* __restrict__ Vh, __half* __restrict__ Ch)
{
    extern __shared__ __align__(16) float smf[];
    const int tid  = threadIdx.x;
    const int warp = tid >> 5;
    const int lane = tid & 31;
    const int gid  = lane >> 2;
    const int tig  = lane & 3;
    const int wq   = warp & 3;
    const int wk   = warp >> 2;
    const int bh   = blockIdx.y;
    const int qt   = blockIdx.x;
    const int mm   = lane >> 3;
    const int mr   = lane & 7;

    const uint32_t sb = smem_u32(smf);

    const __half* Qg = Qh + ((size_t)bh * N_ + qt * 128) * DH_;
    const __half* Kg = Kh + (size_t)bh * N_ * DH_;
    const __half* Vg = Vh + (size_t)bh * N_ * DH_;

    // ---- Q fp16 A-frags (pre-scaled at projection): direct uint loads ----
    uint32_t qa[2][2][4];
#pragma unroll
    for (int m = 0; m < 2; m++) {
        const __half* r0 = Qg + (size_t)(wq * 32 + m * 16 + gid) * DH_;
        const __half* r1 = r0 + 8 * DH_;
#pragma unroll
        for (int h = 0; h < 2; h++) {
            int k0 = h * 16 + 2 * tig;
            qa[m][h][0] = *(const uint32_t*)(r0 + k0);
            qa[m][h][1] = *(const uint32_t*)(r1 + k0);
            qa[m][h][2] = *(const uint32_t*)(r0 + k0 + 8);
            qa[m][h][3] = *(const uint32_t*)(r1 + k0 + 8);
        }
    }

    float oacc[2][4][4];
#pragma unroll
    for (int m = 0; m < 2; m++)
#pragma unroll
        for (int n = 0; n < 4; n++)
#pragma unroll
            for (int r = 0; r < 4; r++) oacc[m][n][r] = 0.f;
    float lp[2][2] = {{0.f, 0.f}, {0.f, 0.f}};

    // ---- cp.async tile loader: K,V 128 x 64B rows -> 80B stride SMEM ----
    auto load_tile = [&](int t, int buf) {
        uint32_t kd = sb + (buf ? KB1 : KB0);
        uint32_t vd = sb + (buf ? VB1 : VB0);
        const char* ks = (const char*)(Kg + (size_t)t * 128 * DH_);
        const char* vs = (const char*)(Vg + (size_t)t * 128 * DH_);
#pragma unroll
        for (int r = 0; r < 2; r++) {
            int idx = tid + r * 256;           // 0..511
            int row = idx >> 2, c = idx & 3;
            cpa16(kd + row * 80 + c * 16, ks + (size_t)row * 64 + c * 16);
            cpa16(vd + row * 80 + c * 16, vs + (size_t)row * 64 + c * 16);
        }
    };

    load_tile(0, 0);
    cp_commit();

    for (int t = 0; t < NTILE; t++) {
        const int buf = t & 1;
        cp_wait<0>();
        __syncthreads();
        if (t + 1 < NTILE) {
            load_tile(t + 1, buf ^ 1);
            cp_commit();
        }

        const uint32_t kbb = sb + (buf ? KB1 : KB0);
        const uint32_t vbb = sb + (buf ? VB1 : VB0);

#pragma unroll
        for (int g = 0; g < 4; g++) {
            const int kb = wk * 64 + g * 16;

            // ---- S = (scaled Q)·K^T − C2, fp16 MMA ----
            float s[2][2][4];
#pragma unroll
            for (int m = 0; m < 2; m++)
#pragma unroll
                for (int j = 0; j < 2; j++)
#pragma unroll
                    for (int r = 0; r < 4; r++) s[m][j][r] = -C2F;

#pragma unroll
            for (int h = 0; h < 2; h++) {
                uint32_t kr[4];
                uint32_t addr = kbb
                    + (uint32_t)(kb + (mm >> 1) * 8 + mr) * 80
                    + (uint32_t)((mm & 1) * 16 + h * 32);
                ldsm4(kr, addr);
                mma_f16(s[0][0], qa[0][h], kr[0], kr[1]);
                mma_f16(s[0][1], qa[0][h], kr[2], kr[3]);
                mma_f16(s[1][0], qa[1][h], kr[0], kr[1]);
                mma_f16(s[1][1], qa[1][h], kr[2], kr[3]);
            }

            // ---- p = 2^s in fp16 pairs; C-frag == A-frag identity ----
            uint32_t aP[2][4];
#pragma unroll
            for (int m = 0; m < 2; m++) {
                aP[m][0] = h2ex2(f16x2(s[m][0][1], s[m][0][0]));
                aP[m][1] = h2ex2(f16x2(s[m][0][3], s[m][0][2]));
                aP[m][2] = h2ex2(f16x2(s[m][1][1], s[m][1][0]));
                aP[m][3] = h2ex2(f16x2(s[m][1][3], s[m][1][2]));
                float2 f0 = h2f2(hadd2(aP[m][0], aP[m][2]));
                float2 f1 = h2f2(hadd2(aP[m][1], aP[m][3]));
                lp[m][0] += f0.x + f0.y;
                lp[m][1] += f1.x + f1.y;
            }

            // ---- O += P·V via trans ldmatrix + fp16 MMA ----
#pragma unroll
            for (int h = 0; h < 2; h++) {
                uint32_t vr[4];
                uint32_t addr = vbb
                    + (uint32_t)(kb + (mm & 1) * 8 + mr) * 80
                    + (uint32_t)((mm >> 1) * 8 + h * 16) * 2;
                ldsm4t(vr, addr);
                mma_f16(oacc[0][2 * h],     aP[0], vr[0], vr[1]);
                mma_f16(oacc[0][2 * h + 1], aP[0], vr[2], vr[3]);
                mma_f16(oacc[1][2 * h],     aP[1], vr[0], vr[1]);
                mma_f16(oacc[1][2 * h + 1], aP[1], vr[2], vr[3]);
            }
        }
    }
    __syncthreads();   // all warps done with SMEM buffers

    // ---- combine key-halves via SMEM scratch ----
    float* sc = smf + wq * 1152;
    if (wk == 1) {
        int idx = 0;
#pragma unroll
        for (int m = 0; m < 2; m++)
#pragma unroll
            for (int n = 0; n < 4; n++)
#pragma unroll
                for (int r = 0; r < 4; r++)
                    sc[(idx++) * 32 + lane] = oacc[m][n][r];
#pragma unroll
        for (int m = 0; m < 2; m++)
#pragma unroll
            for (int r = 0; r < 2; r++)
                sc[1024 + (m * 2 + r) * 32 + lane] = lp[m][r];
    }
    __syncthreads();
    if (wk == 0) {
        int idx = 0;
#pragma unroll
        for (int m = 0; m < 2; m++)
#pragma unroll
            for (int n = 0; n < 4; n++)
#pragma unroll
                for (int r = 0; r < 4; r++)
                    oacc[m][n][r] += sc[(idx++) * 32 + lane];
#pragma unroll
        for (int m = 0; m < 2; m++)
#pragma unroll
            for (int r = 0; r < 2; r++)
                lp[m][r] += sc[1024 + (m * 2 + r) * 32 + lane];

#pragma unroll
        for (int m = 0; m < 2; m++)
#pragma unroll
            for (int r = 0; r < 2; r++) {
                float v = lp[m][r];
                v += __shfl_xor_sync(0xFFFFFFFFu, v, 1);
                v += __shfl_xor_sync(0xFFFFFFFFu, v, 2);
                lp[m][r] = 1.0f / v;
            }

        const int b  = bh >> 3;
        const int hh = bh & 7;
#pragma unroll
        for (int m = 0; m < 2; m++) {
            int q0 = qt * 128 + wq * 32 + m * 16 + gid;
#pragma unroll
            for (int n = 0; n < 4; n++) {
                int col = hh * 32 + n * 8 + 2 * tig;
                __half* p0 = Ch + (size_t)(b * N_ + q0) * D_ + col;
                __half* p1 = Ch + (size_t)(b * N_ + q0 + 8) * D_ + col;
                *(uint32_t*)p0 = f16x2(oacc[m][n][1] * lp[m][0],
                                       oacc[m][n][0] * lp[m][0]);
                *(uint32_t*)p1 = f16x2(oacc[m][n][3] * lp[m][1],
                                       oacc[m][n][2] * lp[m][1]);
            }
        }
    }
}

// ---------------------------------------------------------------------------
extern "C" void kernel_launch(void* const* d_in, const int* in_sizes, int n_in,
                              void* d_out, int out_size)
{
    const float* x  = (const float*)d_in[0];
    const float* Wq = (const float*)d_in[1];
    const float* bq = (const float*)d_in[2];
    const float* Wk = (const float*)d_in[3];
    const float* bk = (const float*)d_in[4];
    const float* Wv = (const float*)d_in[5];
    const float* bv = (const float*)d_in[6];
    const float* Wo = (const float*)d_in[7];
    const float* bo = (const float*)d_in[8];
    float* out = (float*)d_out;

    __half *qh, *kh, *vh, *xh, *wh, *ctxh;
    cudaGetSymbolAddress((void**)&qh,   g_qh_);
    cudaGetSymbolAddress((void**)&kh,   g_kh_);
    cudaGetSymbolAddress((void**)&vh,   g_vh_);
    cudaGetSymbolAddress((void**)&xh,   g_xh_);
    cudaGetSymbolAddress((void**)&wh,   g_wh_);
    cudaGetSymbolAddress((void**)&ctxh, g_ctxh_);

    cudaFuncSetAttribute(gemm_mma_kernel<1>,
                         cudaFuncAttributeMaxDynamicSharedMemorySize, GSM_BYTES);
    cudaFuncSetAttribute(gemm_mma_kernel<0>,
                         cudaFuncAttributeMaxDynamicSharedMemorySize, GSM_BYTES);
    cudaFuncSetAttribute(attn_mma_kernel,
                         cudaFuncAttributeMaxDynamicSharedMemorySize,
                         SMEM_ATTN_BYTES);

    cvt_kernel<<<296, 256>>>(x, Wq, Wk, Wv, Wo, xh, wh);

    dim3 qkv_grid(256 / 64, M_ / 128, 3);    // (4, 36, 3)
    gemm_mma_kernel<1><<<qkv_grid, 256, GSM_BYTES>>>(
        xh, wh, bq, bk, bv, qh, kh, vh, nullptr);

    dim3 agrid(NTILE, BH_);                  // (18, 16)
    attn_mma_kernel<<<agrid, 256, SMEM_ATTN_BYTES>>>(qh, kh, vh, ctxh);

    dim3 o_grid(256 / 64, M_ / 128, 1);      // (4, 36, 1)
    gemm_mma_kernel<0><<<o_grid, 256, GSM_BYTES>>>(
        ctxh, wh + 3 * D_ * D_, bo, bo, bo, nullptr, nullptr, nullptr, out);
}